// round 2
// baseline (speedup 1.0000x reference)
#include <cuda_runtime.h>
#include <math.h>

// ---------------- problem constants ----------------
#define BB     8
#define NTOK   1024
#define DD     256
#define LL     4
#define MFF    1024
#define HH     8
#define DHEAD  32
#define NT     (BB*NTOK)      // 8192 tokens
#define KC     64             // clusters
#define KM_IT  10

// ---------------- scratch (static device globals; no allocation allowed) ----
__device__ float g_x   [NT*DD];        // running residual stream
__device__ float g_xn  [NT*DD];        // layernorm output
__device__ float g_q   [NT*DD];        // q projection
__device__ float g_kv  [NT*2*DD];      // k|v projection
__device__ float g_ao  [NT*DD];        // attention output
__device__ float g_hh  [NT*MFF];       // ffn hidden
__device__ float g_xsq [NT];           // per-point |x|^2
__device__ float g_cent[KC*DD];        // kmeans centers
__device__ float g_csq [KC];           // per-center |c|^2
__device__ float g_csum[KC*DD];        // segment sums
__device__ float g_ccnt[KC];           // segment counts
__device__ int   g_lab [NT];           // labels
__device__ float g_cpro[KC*DD];        // centers @ kW + kb

// ---------------- small helpers ----------------
__device__ __forceinline__ float gelu_f(float x) {
    return 0.5f * x * (1.0f + erff(x * 0.7071067811865476f));
}

// block (256 threads) reduce-sum; result broadcast to all threads via smem
__device__ __forceinline__ float blockSum256(float v) {
    __shared__ float red[8];
    int t = threadIdx.x;
    #pragma unroll
    for (int o = 16; o > 0; o >>= 1) v += __shfl_xor_sync(0xffffffffu, v, o);
    if ((t & 31) == 0) red[t >> 5] = v;
    __syncthreads();
    float s = 0.f;
    if (t == 0) {
        #pragma unroll
        for (int i = 0; i < 8; i++) s += red[i];
        red[0] = s;
    }
    __syncthreads();
    s = red[0];
    __syncthreads();
    return s;
}

// ---------------- elementwise copy ----------------
__global__ void copy_kernel(const float* __restrict__ src, float* __restrict__ dst, int n) {
    int i = blockIdx.x * blockDim.x + threadIdx.x;
    if (i < n) dst[i] = src[i];
}

// ---------------- layernorm: one block (256 thr) per row of 256 ----------------
__global__ void ln_kernel(const float* __restrict__ x, const float* __restrict__ g,
                          const float* __restrict__ b, float* __restrict__ out) {
    int row = blockIdx.x;
    int t = threadIdx.x;
    float v = x[(size_t)row * DD + t];
    float mean = blockSum256(v) * (1.0f / DD);
    float d = v - mean;
    float var = blockSum256(d * d) * (1.0f / DD);
    out[(size_t)row * DD + t] = d * rsqrtf(var + 1e-5f) * g[t] + b[t];
}

// ---------------- row sum-of-squares (rows of 256) ----------------
__global__ void rowsumsq_kernel(const float* __restrict__ x, float* __restrict__ out) {
    int row = blockIdx.x;
    int t = threadIdx.x;
    float v = x[(size_t)row * DD + t];
    float s = blockSum256(v * v);
    if (t == 0) out[row] = s;
}

// ---------------- fp32 tiled GEMM: C = A[MxK] @ B[KxN] (+bias)(+gelu)(+res) ---
// BM=BN=128, BK=8, 256 threads, 8x8 microtile. N must be multiple of 128,
// K multiple of 8; M arbitrary (guarded).
__global__ __launch_bounds__(256)
void gemm_kernel(const float* __restrict__ A, const float* __restrict__ Bm,
                 const float* __restrict__ bias, const float* __restrict__ res,
                 float* __restrict__ C, int M, int N, int K, int act) {
    __shared__ float As[8][128];
    __shared__ float Bs[8][128];
    const int m0 = blockIdx.y * 128;
    const int n0 = blockIdx.x * 128;
    const int t  = threadIdx.x;
    const int tx = t & 15;        // 0..15 -> 8 cols each
    const int ty = t >> 4;        // 0..15 -> 8 rows each

    float acc[8][8];
    #pragma unroll
    for (int i = 0; i < 8; i++)
        #pragma unroll
        for (int j = 0; j < 8; j++) acc[i][j] = 0.f;

    const int arow = t >> 1, aseg = t & 1;          // A: 128 rows x 8 cols
    const int brow = t >> 5, bcol = (t & 31) * 4;   // B: 8 rows x 128 cols

    for (int k0 = 0; k0 < K; k0 += 8) {
        float4 av = make_float4(0.f, 0.f, 0.f, 0.f);
        if (m0 + arow < M)
            av = *(const float4*)&A[(size_t)(m0 + arow) * K + k0 + aseg * 4];
        As[aseg * 4 + 0][arow] = av.x;
        As[aseg * 4 + 1][arow] = av.y;
        As[aseg * 4 + 2][arow] = av.z;
        As[aseg * 4 + 3][arow] = av.w;
        float4 bv = *(const float4*)&Bm[(size_t)(k0 + brow) * N + n0 + bcol];
        *(float4*)&Bs[brow][bcol] = bv;
        __syncthreads();

        #pragma unroll
        for (int kk = 0; kk < 8; kk++) {
            float a[8], bb[8];
            *(float4*)&a[0]  = *(const float4*)&As[kk][ty * 8];
            *(float4*)&a[4]  = *(const float4*)&As[kk][ty * 8 + 4];
            *(float4*)&bb[0] = *(const float4*)&Bs[kk][tx * 8];
            *(float4*)&bb[4] = *(const float4*)&Bs[kk][tx * 8 + 4];
            #pragma unroll
            for (int i = 0; i < 8; i++)
                #pragma unroll
                for (int j = 0; j < 8; j++) acc[i][j] += a[i] * bb[j];
        }
        __syncthreads();
    }

    #pragma unroll
    for (int i = 0; i < 8; i++) {
        int row = m0 + ty * 8 + i;
        if (row < M) {
            size_t base = (size_t)row * N;
            #pragma unroll
            for (int j = 0; j < 8; j++) {
                int col = n0 + tx * 8 + j;
                float v = acc[i][j];
                if (bias) v += bias[col];
                if (act == 1) v = gelu_f(v);
                if (res) v += res[base + col];
                C[base + col] = v;
            }
        }
    }
}

// ---------------- flash attention: grid(16 qtiles, 8 heads, 8 batch) ----------
// 64 threads; each thread owns one q row (dh=32 in registers), online softmax.
__global__ __launch_bounds__(64)
void attn_kernel(const float* __restrict__ q, const float* __restrict__ kv,
                 float* __restrict__ out) {
    __shared__ float Ks[64][32];
    __shared__ float Vs[64][32];
    __shared__ float Ss[64][65];   // padded: no bank conflicts
    const int qt = blockIdx.x, h = blockIdx.y, b = blockIdx.z;
    const int t = threadIdx.x;
    const float scale = 0.17677669529663687f;  // 1/sqrt(32)

    const int qrow = qt * 64 + t;
    const float* qp = q + ((size_t)(b * NTOK) + qrow) * DD + h * DHEAD;
    float qr[32];
    #pragma unroll
    for (int d = 0; d < 32; d++) qr[d] = qp[d] * scale;

    float o[32];
    #pragma unroll
    for (int d = 0; d < 32; d++) o[d] = 0.f;
    float m = -1e30f, l = 0.f;

    for (int kt = 0; kt < NTOK; kt += 64) {
        const float* kbase = kv + ((size_t)(b * NTOK) + kt) * (2 * DD) + h * DHEAD;
        #pragma unroll
        for (int i = 0; i < 8; i++) {
            int idx = i * 64 + t;              // float4 index 0..511
            int r = idx >> 3, c4 = (idx & 7) * 4;
            *(float4*)&Ks[r][c4] = *(const float4*)&kbase[(size_t)r * (2 * DD) + c4];
            *(float4*)&Vs[r][c4] = *(const float4*)&kbase[(size_t)r * (2 * DD) + DD + c4];
        }
        __syncthreads();

        float tmax = -1e30f;
        #pragma unroll 4
        for (int j = 0; j < 64; j++) {
            float s = 0.f;
            #pragma unroll
            for (int d = 0; d < 32; d++) s += qr[d] * Ks[j][d];
            Ss[t][j] = s;
            tmax = fmaxf(tmax, s);
        }
        float mnew = fmaxf(m, tmax);
        float corr = __expf(m - mnew);
        l *= corr;
        #pragma unroll
        for (int d = 0; d < 32; d++) o[d] *= corr;
        #pragma unroll 2
        for (int j = 0; j < 64; j++) {
            float p = __expf(Ss[t][j] - mnew);
            l += p;
            #pragma unroll
            for (int d = 0; d < 32; d++) o[d] += p * Vs[j][d];
        }
        m = mnew;
        __syncthreads();
    }

    float inv = 1.f / l;
    float* op = out + ((size_t)(b * NTOK) + qrow) * DD + h * DHEAD;
    #pragma unroll
    for (int d = 0; d < 32; d++) op[d] = o[d] * inv;
}

// ---------------- kmeans: init centers from first 64 rows ----------------
__global__ void initcent_kernel(const float* __restrict__ x, float* __restrict__ cent) {
    cent[(size_t)blockIdx.x * DD + threadIdx.x] = x[(size_t)blockIdx.x * DD + threadIdx.x];
}

// ---------------- kmeans assign: 128 points/block, 64 centers in registers ----
__global__ __launch_bounds__(128)
void assign_kernel(const float* __restrict__ x, const float* __restrict__ cent,
                   const float* __restrict__ xsq, const float* __restrict__ csq,
                   int* __restrict__ lab) {
    __shared__ float Xs[128][33];   // padded
    __shared__ float Cs[64][32];
    const int t = threadIdx.x;
    const int p0 = blockIdx.x * 128;

    float dot[64];
    #pragma unroll
    for (int c = 0; c < 64; c++) dot[c] = 0.f;

    for (int dc = 0; dc < DD; dc += 32) {
        #pragma unroll
        for (int i = 0; i < 8; i++) {               // 1024 float4 / 128 thr
            int idx = i * 128 + t;
            int r = idx >> 3, c4 = (idx & 7) * 4;
            float4 v = *(const float4*)&x[(size_t)(p0 + r) * DD + dc + c4];
            Xs[r][c4 + 0] = v.x; Xs[r][c4 + 1] = v.y;
            Xs[r][c4 + 2] = v.z; Xs[r][c4 + 3] = v.w;
        }
        #pragma unroll
        for (int i = 0; i < 4; i++) {               // 512 float4 / 128 thr
            int idx = i * 128 + t;
            int r = idx >> 3, c4 = (idx & 7) * 4;
            *(float4*)&Cs[r][c4] = *(const float4*)&cent[(size_t)r * DD + dc + c4];
        }
        __syncthreads();
        #pragma unroll 4
        for (int d = 0; d < 32; d++) {
            float xv = Xs[t][d];
            #pragma unroll
            for (int c = 0; c < 64; c++) dot[c] += xv * Cs[c][d];
        }
        __syncthreads();
    }

    float xs = xsq[p0 + t];
    float best = 3.4e38f;
    int bl = 0;
    #pragma unroll
    for (int c = 0; c < 64; c++) {
        float dd = xs - 2.f * dot[c] + csq[c];
        if (dd < best) { best = dd; bl = c; }   // strict < keeps first index (argmin)
    }
    lab[p0 + t] = bl;
}

// ---------------- deterministic segment sum: one block per center -------------
__global__ __launch_bounds__(256)
void segsum_kernel(const float* __restrict__ x, const int* __restrict__ lab,
                   float* __restrict__ sums, float* __restrict__ cnts) {
    const int c = blockIdx.x;
    const int t = threadIdx.x;
    __shared__ int labs[256];
    float acc = 0.f;
    int cnt = 0;
    for (int p0 = 0; p0 < NT; p0 += 256) {
        labs[t] = lab[p0 + t];
        __syncthreads();
        #pragma unroll 8
        for (int i = 0; i < 256; i++) {
            if (labs[i] == c) { acc += x[(size_t)(p0 + i) * DD + t]; cnt++; }
        }
        __syncthreads();
    }
    sums[(size_t)c * DD + t] = acc;
    if (t == 0) cnts[c] = (float)cnt;
}

__global__ void update_kernel(float* __restrict__ cent, const float* __restrict__ sums,
                              const float* __restrict__ cnts) {
    int c = blockIdx.x, t = threadIdx.x;
    float cnt = cnts[c];
    if (cnt > 0.f) cent[(size_t)c * DD + t] = sums[(size_t)c * DD + t] / fmaxf(cnt, 1.f);
}

__global__ void gather_kernel(const float* __restrict__ cproj, const int* __restrict__ lab,
                              float* __restrict__ out) {
    int p = blockIdx.x, t = threadIdx.x;
    out[(size_t)p * DD + t] = cproj[(size_t)lab[p] * DD + t];
}

// ---------------- host orchestration ----------------
extern "C" void kernel_launch(void* const* d_in, const int* in_sizes, int n_in,
                              void* d_out, int out_size) {
    const float* x_in = (const float*)d_in[0];
    const float* ln1g = (const float*)d_in[1];
    const float* ln1b = (const float*)d_in[2];
    const float* Wq   = (const float*)d_in[3];
    const float* Wkv  = (const float*)d_in[4];
    const float* Wo   = (const float*)d_in[5];
    const float* bo   = (const float*)d_in[6];
    const float* ln2g = (const float*)d_in[7];
    const float* ln2b = (const float*)d_in[8];
    const float* W1   = (const float*)d_in[9];
    const float* b1   = (const float*)d_in[10];
    const float* W2   = (const float*)d_in[11];
    const float* b2   = (const float*)d_in[12];
    const float* kW   = (const float*)d_in[13];
    const float* kb   = (const float*)d_in[14];
    float* out = (float*)d_out;

    float *p_x, *p_xn, *p_q, *p_kv, *p_ao, *p_h, *p_xsq, *p_cent, *p_csq, *p_csum, *p_ccnt, *p_cpro;
    int *p_lab;
    cudaGetSymbolAddress((void**)&p_x,    g_x);
    cudaGetSymbolAddress((void**)&p_xn,   g_xn);
    cudaGetSymbolAddress((void**)&p_q,    g_q);
    cudaGetSymbolAddress((void**)&p_kv,   g_kv);
    cudaGetSymbolAddress((void**)&p_ao,   g_ao);
    cudaGetSymbolAddress((void**)&p_h,    g_hh);
    cudaGetSymbolAddress((void**)&p_xsq,  g_xsq);
    cudaGetSymbolAddress((void**)&p_cent, g_cent);
    cudaGetSymbolAddress((void**)&p_csq,  g_csq);
    cudaGetSymbolAddress((void**)&p_csum, g_csum);
    cudaGetSymbolAddress((void**)&p_ccnt, g_ccnt);
    cudaGetSymbolAddress((void**)&p_lab,  g_lab);
    cudaGetSymbolAddress((void**)&p_cpro, g_cpro);

    // x -> residual stream
    copy_kernel<<<(NT * DD + 255) / 256, 256>>>(x_in, p_x, NT * DD);

    for (int l = 0; l < LL; l++) {
        const float* wq  = Wq  + (size_t)l * DD * DD;
        const float* wkv = Wkv + (size_t)l * DD * (2 * DD);
        const float* wo  = Wo  + (size_t)l * DD * DD;
        const float* w1  = W1  + (size_t)l * DD * MFF;
        const float* w2  = W2  + (size_t)l * MFF * DD;

        // ln1
        ln_kernel<<<NT, 256>>>(p_x, ln1g + l * DD, ln1b + l * DD, p_xn);
        // q, kv projections
        gemm_kernel<<<dim3(DD / 128, NT / 128), 256>>>(p_xn, wq,  nullptr, nullptr, p_q,  NT, DD,     DD, 0);
        gemm_kernel<<<dim3(2 * DD / 128, NT / 128), 256>>>(p_xn, wkv, nullptr, nullptr, p_kv, NT, 2 * DD, DD, 0);
        // attention
        attn_kernel<<<dim3(NTOK / 64, HH, BB), 64>>>(p_q, p_kv, p_ao);
        // out proj + bias + residual (in place into x)
        gemm_kernel<<<dim3(DD / 128, NT / 128), 256>>>(p_ao, wo, bo + l * DD, p_x, p_x, NT, DD, DD, 0);
        // ln2
        ln_kernel<<<NT, 256>>>(p_x, ln2g + l * DD, ln2b + l * DD, p_xn);
        // ffn up + gelu
        gemm_kernel<<<dim3(MFF / 128, NT / 128), 256>>>(p_xn, w1, b1 + l * MFF, nullptr, p_h, NT, MFF, DD, 1);
        // ffn down + bias + residual
        gemm_kernel<<<dim3(DD / 128, NT / 128), 256>>>(p_h, w2, b2 + l * DD, p_x, p_x, NT, DD, MFF, 0);
    }

    // ---- kmeans ----
    initcent_kernel<<<KC, 256>>>(p_x, p_cent);
    rowsumsq_kernel<<<NT, 256>>>(p_x, p_xsq);

    for (int it = 0; it < KM_IT; it++) {
        rowsumsq_kernel<<<KC, 256>>>(p_cent, p_csq);
        assign_kernel<<<NT / 128, 128>>>(p_x, p_cent, p_xsq, p_csq, p_lab);
        segsum_kernel<<<KC, 256>>>(p_x, p_lab, p_csum, p_ccnt);
        update_kernel<<<KC, 256>>>(p_cent, p_csum, p_ccnt);
    }
    // final assignment
    rowsumsq_kernel<<<KC, 256>>>(p_cent, p_csq);
    assign_kernel<<<NT / 128, 128>>>(p_x, p_cent, p_xsq, p_csq, p_lab);

    // project centers once (centers[labels] @ kW == (centers @ kW)[labels])
    gemm_kernel<<<dim3(DD / 128, 1), 256>>>(p_cent, kW, kb, nullptr, p_cpro, KC, DD, DD, 0);
    gather_kernel<<<NT, 256>>>(p_cpro, p_lab, out);
}

// round 3
// speedup vs baseline: 1.5160x; 1.5160x over previous
#include <cuda_runtime.h>
#include <math.h>

// ---------------- problem constants ----------------
#define BB     8
#define NTOK   1024
#define DD     256
#define LL     4
#define MFF    1024
#define HH     8
#define DHEAD  32
#define NT     (BB*NTOK)      // 8192 tokens
#define KC     64             // clusters
#define KM_IT  10
#define SB     64             // segsum point-blocks (128 points each)

// ---------------- scratch (static device globals; no allocation allowed) ----
__device__ float g_x   [NT*DD];        // running residual stream
__device__ float g_xn  [NT*DD];        // layernorm output
__device__ float g_q   [NT*DD];        // q projection
__device__ float g_kv  [NT*2*DD];      // k|v projection
__device__ float g_ao  [NT*DD];        // attention output
__device__ float g_hh  [NT*MFF];       // ffn hidden
__device__ float g_xsq [NT];           // per-point |x|^2
__device__ float g_cent[KC*DD];        // kmeans centers
__device__ float g_csq [KC];           // per-center |c|^2
__device__ float g_csum[KC*DD];        // segment sums
__device__ float g_ccnt[KC];           // segment counts
__device__ int   g_lab [NT];           // labels
__device__ float g_cpro[KC*DD];        // centers @ kW + kb
__device__ float g_part[SB*KC*DD];     // segsum partials (16 MB)
__device__ float g_pcnt[SB*KC];        // segsum partial counts

// ---------------- small helpers ----------------
__device__ __forceinline__ float gelu_f(float x) {
    return 0.5f * x * (1.0f + erff(x * 0.7071067811865476f));
}

__device__ __forceinline__ float warpSum(float v) {
    #pragma unroll
    for (int o = 16; o > 0; o >>= 1) v += __shfl_xor_sync(0xffffffffu, v, o);
    return v;
}

// ---------------- elementwise copy (float4) ----------------
__global__ void copy_kernel(const float4* __restrict__ src, float4* __restrict__ dst, int n4) {
    int i = blockIdx.x * blockDim.x + threadIdx.x;
    if (i < n4) dst[i] = src[i];
}

// ---------------- layernorm: one WARP per row of 256 ----------------
__global__ void ln_kernel(const float* __restrict__ x, const float* __restrict__ g,
                          const float* __restrict__ b, float* __restrict__ out) {
    int row  = (blockIdx.x * blockDim.x + threadIdx.x) >> 5;
    int lane = threadIdx.x & 31;
    const float* xp = x + (size_t)row * DD;
    float4 a = *(const float4*)&xp[lane * 4];
    float4 c = *(const float4*)&xp[128 + lane * 4];
    float s = a.x + a.y + a.z + a.w + c.x + c.y + c.z + c.w;
    float mean = warpSum(s) * (1.0f / DD);
    float4 da = make_float4(a.x - mean, a.y - mean, a.z - mean, a.w - mean);
    float4 dc = make_float4(c.x - mean, c.y - mean, c.z - mean, c.w - mean);
    float v = da.x*da.x + da.y*da.y + da.z*da.z + da.w*da.w
            + dc.x*dc.x + dc.y*dc.y + dc.z*dc.z + dc.w*dc.w;
    float rs = rsqrtf(warpSum(v) * (1.0f / DD) + 1e-5f);
    float4 g0 = *(const float4*)&g[lane * 4];
    float4 g1 = *(const float4*)&g[128 + lane * 4];
    float4 b0 = *(const float4*)&b[lane * 4];
    float4 b1 = *(const float4*)&b[128 + lane * 4];
    float* op = out + (size_t)row * DD;
    float4 o0 = make_float4(da.x*rs*g0.x + b0.x, da.y*rs*g0.y + b0.y,
                            da.z*rs*g0.z + b0.z, da.w*rs*g0.w + b0.w);
    float4 o1 = make_float4(dc.x*rs*g1.x + b1.x, dc.y*rs*g1.y + b1.y,
                            dc.z*rs*g1.z + b1.z, dc.w*rs*g1.w + b1.w);
    *(float4*)&op[lane * 4] = o0;
    *(float4*)&op[128 + lane * 4] = o1;
}

// ---------------- row sum-of-squares: one WARP per row of 256 ----------------
__global__ void rowsumsq_kernel(const float* __restrict__ x, float* __restrict__ out) {
    int row  = (blockIdx.x * blockDim.x + threadIdx.x) >> 5;
    int lane = threadIdx.x & 31;
    const float* xp = x + (size_t)row * DD;
    float4 a = *(const float4*)&xp[lane * 4];
    float4 c = *(const float4*)&xp[128 + lane * 4];
    float s = a.x*a.x + a.y*a.y + a.z*a.z + a.w*a.w
            + c.x*c.x + c.y*c.y + c.z*c.z + c.w*c.w;
    s = warpSum(s);
    if (lane == 0) out[row] = s;
}

// ---------------- fp32 GEMM: C = A[MxK] @ B[KxN] (+bias)(+gelu)(+res) -------
// BK=16, double-buffered smem, 8x8 microtile. M % BM == 0, N % BN == 0,
// K % 16 == 0 required (true for all launches here).
template<int BM, int BN>
__global__ __launch_bounds__(BM*BN/64)
void gemm_t(const float* __restrict__ A, const float* __restrict__ Bm,
            const float* __restrict__ bias, const float* __restrict__ res,
            float* __restrict__ C, int M, int N, int K, int act) {
    constexpr int BK = 16;
    constexpr int THREADS = BM * BN / 64;
    constexpr int NA = (BM * BK / 4) / THREADS;
    constexpr int NB = (BK * BN / 4) / THREADS;
    __shared__ float As[2][BK][BM];
    __shared__ float Bs[2][BK][BN];
    const int m0 = blockIdx.y * BM;
    const int n0 = blockIdx.x * BN;
    const int t  = threadIdx.x;
    const int tx = t % (BN / 8);
    const int ty = t / (BN / 8);

    float acc[8][8];
    #pragma unroll
    for (int i = 0; i < 8; i++)
        #pragma unroll
        for (int j = 0; j < 8; j++) acc[i][j] = 0.f;

    // ---- load tile 0 directly ----
    #pragma unroll
    for (int i = 0; i < NA; i++) {
        int idx = i * THREADS + t;
        int r = idx >> 2, c4 = (idx & 3) * 4;
        float4 v = *(const float4*)&A[(size_t)(m0 + r) * K + c4];
        As[0][c4+0][r] = v.x; As[0][c4+1][r] = v.y;
        As[0][c4+2][r] = v.z; As[0][c4+3][r] = v.w;
    }
    #pragma unroll
    for (int i = 0; i < NB; i++) {
        int idx = i * THREADS + t;
        int r = idx / (BN / 4), c4 = (idx % (BN / 4)) * 4;
        *(float4*)&Bs[0][r][c4] = *(const float4*)&Bm[(size_t)r * N + n0 + c4];
    }
    __syncthreads();

    auto compute_tile = [&](int bf) {
        #pragma unroll
        for (int kk = 0; kk < BK; kk++) {
            float a[8], bfr[8];
            *(float4*)&a[0]   = *(const float4*)&As[bf][kk][ty * 8];
            *(float4*)&a[4]   = *(const float4*)&As[bf][kk][ty * 8 + 4];
            *(float4*)&bfr[0] = *(const float4*)&Bs[bf][kk][tx * 8];
            *(float4*)&bfr[4] = *(const float4*)&Bs[bf][kk][tx * 8 + 4];
            #pragma unroll
            for (int i = 0; i < 8; i++)
                #pragma unroll
                for (int j = 0; j < 8; j++) acc[i][j] += a[i] * bfr[j];
        }
    };

    int buf = 0;
    for (int k0 = BK; k0 < K; k0 += BK) {
        float4 ra[NA], rb[NB];
        #pragma unroll
        for (int i = 0; i < NA; i++) {
            int idx = i * THREADS + t;
            int r = idx >> 2, c4 = (idx & 3) * 4;
            ra[i] = *(const float4*)&A[(size_t)(m0 + r) * K + k0 + c4];
        }
        #pragma unroll
        for (int i = 0; i < NB; i++) {
            int idx = i * THREADS + t;
            int r = idx / (BN / 4), c4 = (idx % (BN / 4)) * 4;
            rb[i] = *(const float4*)&Bm[(size_t)(k0 + r) * N + n0 + c4];
        }
        compute_tile(buf);
        int nb = buf ^ 1;
        #pragma unroll
        for (int i = 0; i < NA; i++) {
            int idx = i * THREADS + t;
            int r = idx >> 2, c4 = (idx & 3) * 4;
            As[nb][c4+0][r] = ra[i].x; As[nb][c4+1][r] = ra[i].y;
            As[nb][c4+2][r] = ra[i].z; As[nb][c4+3][r] = ra[i].w;
        }
        #pragma unroll
        for (int i = 0; i < NB; i++) {
            int idx = i * THREADS + t;
            int r = idx / (BN / 4), c4 = (idx % (BN / 4)) * 4;
            *(float4*)&Bs[nb][r][c4] = rb[i];
        }
        __syncthreads();
        buf = nb;
    }
    compute_tile(buf);

    // ---- epilogue ----
    #pragma unroll
    for (int i = 0; i < 8; i++) {
        int row = m0 + ty * 8 + i;
        size_t base = (size_t)row * N + n0 + tx * 8;
        #pragma unroll
        for (int jj = 0; jj < 2; jj++) {
            float4 v = make_float4(acc[i][jj*4+0], acc[i][jj*4+1],
                                   acc[i][jj*4+2], acc[i][jj*4+3]);
            if (bias) {
                float4 bb4 = *(const float4*)&bias[n0 + tx * 8 + jj * 4];
                v.x += bb4.x; v.y += bb4.y; v.z += bb4.z; v.w += bb4.w;
            }
            if (act == 1) {
                v.x = gelu_f(v.x); v.y = gelu_f(v.y);
                v.z = gelu_f(v.z); v.w = gelu_f(v.w);
            }
            if (res) {
                float4 r4 = *(const float4*)&res[base + jj * 4];
                v.x += r4.x; v.y += r4.y; v.z += r4.z; v.w += r4.w;
            }
            *(float4*)&C[base + jj * 4] = v;
        }
    }
}

// ---------------- flash attention -------------------------------------------
// grid(8 qtiles of 128, 8 heads, 8 batch), 128 threads; each thread owns one
// q row (dh=32 in regs), K/V tiles of 32 in smem, 32 scores in registers,
// float4 smem loads (broadcast), online softmax.
__global__ __launch_bounds__(128)
void attn_kernel(const float* __restrict__ q, const float* __restrict__ kv,
                 float* __restrict__ out) {
    __shared__ float Ks[32][32];
    __shared__ float Vs[32][32];
    const int h = blockIdx.y, b = blockIdx.z;
    const int t = threadIdx.x;
    const int qrow = blockIdx.x * 128 + t;
    const float scale = 0.17677669529663687f;  // 1/sqrt(32)

    const float* qp = q + ((size_t)(b * NTOK) + qrow) * DD + h * DHEAD;
    float qr[32];
    #pragma unroll
    for (int i = 0; i < 8; i++) {
        float4 v = *(const float4*)&qp[i * 4];
        qr[i*4+0] = v.x * scale; qr[i*4+1] = v.y * scale;
        qr[i*4+2] = v.z * scale; qr[i*4+3] = v.w * scale;
    }
    float o[32];
    #pragma unroll
    for (int d = 0; d < 32; d++) o[d] = 0.f;
    float m = -1e30f, l = 0.f;

    for (int kt = 0; kt < NTOK; kt += 32) {
        const float* kb_ = kv + ((size_t)(b * NTOK) + kt) * (2 * DD) + h * DHEAD;
        #pragma unroll
        for (int i = 0; i < 2; i++) {
            int idx = i * 128 + t;           // 0..255 float4 slots
            int r = idx >> 3, c4 = (idx & 7) * 4;
            *(float4*)&Ks[r][c4] = *(const float4*)&kb_[(size_t)r * (2 * DD) + c4];
            *(float4*)&Vs[r][c4] = *(const float4*)&kb_[(size_t)r * (2 * DD) + DD + c4];
        }
        __syncthreads();

        float s[32];
        float tmax = -1e30f;
        #pragma unroll
        for (int j = 0; j < 32; j++) {
            const float4* kp = (const float4*)&Ks[j][0];
            float acc = 0.f;
            #pragma unroll
            for (int i2 = 0; i2 < 8; i2++) {
                float4 k4 = kp[i2];
                acc += qr[i2*4+0]*k4.x + qr[i2*4+1]*k4.y
                     + qr[i2*4+2]*k4.z + qr[i2*4+3]*k4.w;
            }
            s[j] = acc;
            tmax = fmaxf(tmax, acc);
        }
        float mnew = fmaxf(m, tmax);
        float corr = __expf(m - mnew);
        l *= corr;
        #pragma unroll
        for (int d = 0; d < 32; d++) o[d] *= corr;
        #pragma unroll
        for (int j = 0; j < 32; j++) {
            float p = __expf(s[j] - mnew);
            l += p;
            const float4* vp = (const float4*)&Vs[j][0];
            #pragma unroll
            for (int i2 = 0; i2 < 8; i2++) {
                float4 v4 = vp[i2];
                o[i2*4+0] += p * v4.x; o[i2*4+1] += p * v4.y;
                o[i2*4+2] += p * v4.z; o[i2*4+3] += p * v4.w;
            }
        }
        m = mnew;
        __syncthreads();
    }

    float inv = 1.f / l;
    float* op = out + ((size_t)(b * NTOK) + qrow) * DD + h * DHEAD;
    #pragma unroll
    for (int i = 0; i < 8; i++) {
        float4 v = make_float4(o[i*4+0]*inv, o[i*4+1]*inv, o[i*4+2]*inv, o[i*4+3]*inv);
        *(float4*)&op[i * 4] = v;
    }
}

// ---------------- kmeans: init centers from first 64 rows ----------------
__global__ void initcent_kernel(const float* __restrict__ x, float* __restrict__ cent) {
    cent[(size_t)blockIdx.x * DD + threadIdx.x] = x[(size_t)blockIdx.x * DD + threadIdx.x];
}

// ---------------- kmeans assign: 128 points/block, 64 centers ----------------
__global__ __launch_bounds__(128)
void assign_kernel(const float* __restrict__ x, const float* __restrict__ cent,
                   const float* __restrict__ xsq, const float* __restrict__ csq,
                   int* __restrict__ lab) {
    __shared__ float Xs[128][33];   // padded
    __shared__ float Cs[64][32];
    const int t = threadIdx.x;
    const int p0 = blockIdx.x * 128;

    float dot[64];
    #pragma unroll
    for (int c = 0; c < 64; c++) dot[c] = 0.f;

    for (int dc = 0; dc < DD; dc += 32) {
        #pragma unroll
        for (int i = 0; i < 8; i++) {
            int idx = i * 128 + t;
            int r = idx >> 3, c4 = (idx & 7) * 4;
            float4 v = *(const float4*)&x[(size_t)(p0 + r) * DD + dc + c4];
            Xs[r][c4 + 0] = v.x; Xs[r][c4 + 1] = v.y;
            Xs[r][c4 + 2] = v.z; Xs[r][c4 + 3] = v.w;
        }
        #pragma unroll
        for (int i = 0; i < 4; i++) {
            int idx = i * 128 + t;
            int r = idx >> 3, c4 = (idx & 7) * 4;
            *(float4*)&Cs[r][c4] = *(const float4*)&cent[(size_t)r * DD + dc + c4];
        }
        __syncthreads();
        #pragma unroll 4
        for (int d = 0; d < 32; d++) {
            float xv = Xs[t][d];
            #pragma unroll
            for (int c = 0; c < 64; c++) dot[c] += xv * Cs[c][d];
        }
        __syncthreads();
    }

    float xs = xsq[p0 + t];
    float best = 3.4e38f;
    int bl = 0;
    #pragma unroll
    for (int c = 0; c < 64; c++) {
        float dd = xs - 2.f * dot[c] + csq[c];
        if (dd < best) { best = dd; bl = c; }   // strict < keeps first index (argmin)
    }
    lab[p0 + t] = bl;
}

// ---------------- segment sum phase 1: per-point-block partials --------------
// grid (SB, 2): block handles 128 points x 32 centers. Deterministic.
__global__ __launch_bounds__(256)
void segsum1_kernel(const float* __restrict__ x, const int* __restrict__ lab,
                    float* __restrict__ part, float* __restrict__ pcnt) {
    const int blk = blockIdx.x;
    const int c0  = blockIdx.y * 32;
    const int t = threadIdx.x;             // dim index 0..255
    __shared__ float ps[32][DD];           // 32 KB
    __shared__ int labs[128];
    #pragma unroll
    for (int i = 0; i < 32; i++) ps[i][t] = 0.f;
    if (t < 128) labs[t] = lab[blk * 128 + t];
    __syncthreads();
    const int p0 = blk * 128;
    for (int i = 0; i < 128; i++) {
        int l = labs[i] - c0;
        if ((unsigned)l < 32u)
            ps[l][t] += x[(size_t)(p0 + i) * DD + t];
    }
    for (int c = 0; c < 32; c++)
        part[((size_t)blk * KC + c0 + c) * DD + t] = ps[c][t];
    if (t < 32) {
        int cnt = 0;
        for (int i = 0; i < 128; i++) cnt += (labs[i] == c0 + t);
        pcnt[blk * KC + c0 + t] = (float)cnt;
    }
}

// ---------------- segment sum phase 2: ordered reduce over blocks ------------
__global__ void segsum2_kernel(const float* __restrict__ part, const float* __restrict__ pcnt,
                               float* __restrict__ sums, float* __restrict__ cnts) {
    const int c = blockIdx.x, t = threadIdx.x;
    float acc = 0.f;
    for (int b2 = 0; b2 < SB; b2++) acc += part[((size_t)b2 * KC + c) * DD + t];
    sums[(size_t)c * DD + t] = acc;
    if (t == 0) {
        float cc = 0.f;
        for (int b2 = 0; b2 < SB; b2++) cc += pcnt[b2 * KC + c];
        cnts[c] = cc;
    }
}

__global__ void update_kernel(float* __restrict__ cent, const float* __restrict__ sums,
                              const float* __restrict__ cnts) {
    int c = blockIdx.x, t = threadIdx.x;
    float cnt = cnts[c];
    if (cnt > 0.f) cent[(size_t)c * DD + t] = sums[(size_t)c * DD + t] / fmaxf(cnt, 1.f);
}

// ---------------- project centers: cpro = cent @ kW + kb --------------------
__global__ void cproj_kernel(const float* __restrict__ cent, const float* __restrict__ kW,
                             const float* __restrict__ kb, float* __restrict__ cpro) {
    __shared__ float cr[DD];
    int c = blockIdx.x, t = threadIdx.x;
    cr[t] = cent[(size_t)c * DD + t];
    __syncthreads();
    float acc = kb[t];
    for (int d = 0; d < DD; d++) acc += cr[d] * kW[(size_t)d * DD + t];
    cpro[(size_t)c * DD + t] = acc;
}

__global__ void gather_kernel(const float* __restrict__ cproj, const int* __restrict__ lab,
                              float* __restrict__ out) {
    int p = blockIdx.x, t = threadIdx.x;
    out[(size_t)p * DD + t] = cproj[(size_t)lab[p] * DD + t];
}

// ---------------- host orchestration ----------------
extern "C" void kernel_launch(void* const* d_in, const int* in_sizes, int n_in,
                              void* d_out, int out_size) {
    const float* x_in = (const float*)d_in[0];
    const float* ln1g = (const float*)d_in[1];
    const float* ln1b = (const float*)d_in[2];
    const float* Wq   = (const float*)d_in[3];
    const float* Wkv  = (const float*)d_in[4];
    const float* Wo   = (const float*)d_in[5];
    const float* bo   = (const float*)d_in[6];
    const float* ln2g = (const float*)d_in[7];
    const float* ln2b = (const float*)d_in[8];
    const float* W1   = (const float*)d_in[9];
    const float* b1   = (const float*)d_in[10];
    const float* W2   = (const float*)d_in[11];
    const float* b2   = (const float*)d_in[12];
    const float* kW   = (const float*)d_in[13];
    const float* kb   = (const float*)d_in[14];
    float* out = (float*)d_out;

    float *p_x, *p_xn, *p_q, *p_kv, *p_ao, *p_h, *p_xsq, *p_cent, *p_csq, *p_csum, *p_ccnt, *p_cpro, *p_part, *p_pcnt;
    int *p_lab;
    cudaGetSymbolAddress((void**)&p_x,    g_x);
    cudaGetSymbolAddress((void**)&p_xn,   g_xn);
    cudaGetSymbolAddress((void**)&p_q,    g_q);
    cudaGetSymbolAddress((void**)&p_kv,   g_kv);
    cudaGetSymbolAddress((void**)&p_ao,   g_ao);
    cudaGetSymbolAddress((void**)&p_h,    g_hh);
    cudaGetSymbolAddress((void**)&p_xsq,  g_xsq);
    cudaGetSymbolAddress((void**)&p_cent, g_cent);
    cudaGetSymbolAddress((void**)&p_csq,  g_csq);
    cudaGetSymbolAddress((void**)&p_csum, g_csum);
    cudaGetSymbolAddress((void**)&p_ccnt, g_ccnt);
    cudaGetSymbolAddress((void**)&p_lab,  g_lab);
    cudaGetSymbolAddress((void**)&p_cpro, g_cpro);
    cudaGetSymbolAddress((void**)&p_part, g_part);
    cudaGetSymbolAddress((void**)&p_pcnt, g_pcnt);

    // x -> residual stream
    copy_kernel<<<(NT * DD / 4 + 255) / 256, 256>>>((const float4*)x_in, (float4*)p_x, NT * DD / 4);

    for (int l = 0; l < LL; l++) {
        const float* wq  = Wq  + (size_t)l * DD * DD;
        const float* wkv = Wkv + (size_t)l * DD * (2 * DD);
        const float* wo  = Wo  + (size_t)l * DD * DD;
        const float* w1  = W1  + (size_t)l * DD * MFF;
        const float* w2  = W2  + (size_t)l * MFF * DD;

        // ln1 (warp per row: NT rows, 8 rows/block)
        ln_kernel<<<NT / 8, 256>>>(p_x, ln1g + l * DD, ln1b + l * DD, p_xn);
        // q projection: N=256 -> 128x64 tile, grid (4, 64)
        gemm_t<128,64><<<dim3(DD / 64, NT / 128), 128>>>(p_xn, wq, nullptr, nullptr, p_q, NT, DD, DD, 0);
        // kv projection: N=512 -> 128x128 tile
        gemm_t<128,128><<<dim3(2 * DD / 128, NT / 128), 256>>>(p_xn, wkv, nullptr, nullptr, p_kv, NT, 2 * DD, DD, 0);
        // attention
        attn_kernel<<<dim3(NTOK / 128, HH, BB), 128>>>(p_q, p_kv, p_ao);
        // out proj + bias + residual (in place into x)
        gemm_t<128,64><<<dim3(DD / 64, NT / 128), 128>>>(p_ao, wo, bo + l * DD, p_x, p_x, NT, DD, DD, 0);
        // ln2
        ln_kernel<<<NT / 8, 256>>>(p_x, ln2g + l * DD, ln2b + l * DD, p_xn);
        // ffn up + gelu
        gemm_t<128,128><<<dim3(MFF / 128, NT / 128), 256>>>(p_xn, w1, b1 + l * MFF, nullptr, p_h, NT, MFF, DD, 1);
        // ffn down + bias + residual
        gemm_t<128,64><<<dim3(DD / 64, NT / 128), 128>>>(p_h, w2, b2 + l * DD, p_x, p_x, NT, DD, MFF, 0);
    }

    // ---- kmeans ----
    initcent_kernel<<<KC, 256>>>(p_x, p_cent);
    rowsumsq_kernel<<<NT / 8, 256>>>(p_x, p_xsq);

    for (int it = 0; it < KM_IT; it++) {
        rowsumsq_kernel<<<KC / 8, 256>>>(p_cent, p_csq);
        assign_kernel<<<NT / 128, 128>>>(p_x, p_cent, p_xsq, p_csq, p_lab);
        segsum1_kernel<<<dim3(SB, 2), 256>>>(p_x, p_lab, p_part, p_pcnt);
        segsum2_kernel<<<KC, 256>>>(p_part, p_pcnt, p_csum, p_ccnt);
        update_kernel<<<KC, 256>>>(p_cent, p_csum, p_ccnt);
    }
    // final assignment
    rowsumsq_kernel<<<KC / 8, 256>>>(p_cent, p_csq);
    assign_kernel<<<NT / 128, 128>>>(p_x, p_cent, p_xsq, p_csq, p_lab);

    // project centers once (centers[labels] @ kW == (centers @ kW)[labels])
    cproj_kernel<<<KC, 256>>>(p_cent, kW, kb, p_cpro);
    gather_kernel<<<NT, 256>>>(p_cpro, p_lab, out);
}

// round 5
// speedup vs baseline: 1.8393x; 1.2132x over previous
#include <cuda_runtime.h>
#include <cuda_bf16.h>
#include <math.h>
#include <stdint.h>

// ---------------- problem constants ----------------
#define BB     8
#define NTOK   1024
#define DD     256
#define LL     4
#define MFF    1024
#define HH     8
#define DHEAD  32
#define NT     (BB*NTOK)      // 8192 tokens
#define KC     64             // clusters
#define KM_IT  10
#define SB     64             // segsum point-blocks (128 points each)

// weight-transpose scratch offsets (elements, per layer base = l*786432)
#define WT_LAYER 786432
#define WQ_OFF   0
#define WKV_OFF  65536
#define WO_OFF   196608
#define W1_OFF   262144
#define W2_OFF   524288

// ---------------- scratch (static device globals; no allocation allowed) ----
__device__ float g_x   [NT*DD];        // running residual stream (fp32)
__device__ float g_q   [NT*DD];        // q projection (fp32)
__device__ float g_kv  [NT*2*DD];      // k|v projection (fp32)
__device__ __nv_bfloat16 g_xnh[NT*DD]; // layernorm out hi
__device__ __nv_bfloat16 g_xnl[NT*DD]; // layernorm out lo
__device__ __nv_bfloat16 g_aoh[NT*DD]; // attention out hi
__device__ __nv_bfloat16 g_aol[NT*DD]; // attention out lo
__device__ __nv_bfloat16 g_hh [NT*MFF];// ffn hidden hi
__device__ __nv_bfloat16 g_hl [NT*MFF];// ffn hidden lo
__device__ __nv_bfloat16 g_wth[LL*WT_LAYER]; // transposed weights hi
__device__ __nv_bfloat16 g_wtl[LL*WT_LAYER]; // transposed weights lo
__device__ float g_xsq [NT];
__device__ float g_cent[KC*DD];
__device__ float g_csq [KC];
__device__ float g_csum[KC*DD];
__device__ float g_ccnt[KC];
__device__ int   g_lab [NT];
__device__ float g_cpro[KC*DD];
__device__ float g_part[SB*KC*DD];
__device__ float g_pcnt[SB*KC];

// ---------------- small helpers ----------------
__device__ __forceinline__ float gelu_f(float x) {
    return 0.5f * x * (1.0f + erff(x * 0.7071067811865476f));
}
__device__ __forceinline__ float warpSum(float v) {
    #pragma unroll
    for (int o = 16; o > 0; o >>= 1) v += __shfl_xor_sync(0xffffffffu, v, o);
    return v;
}
__device__ __forceinline__ void splitf(float v, __nv_bfloat16& h, __nv_bfloat16& l) {
    h = __float2bfloat16(v);
    l = __float2bfloat16(v - __bfloat162float(h));
}
__device__ __forceinline__ uint32_t smem_u32(const void* p) {
    uint32_t a;
    asm("{ .reg .u64 t; cvta.to.shared.u64 t, %1; cvt.u32.u64 %0, t; }" : "=r"(a) : "l"(p));
    return a;
}

// ---------------- mma.sync helpers (sm_80+ path; valid on sm_103 base) ------
__device__ __forceinline__ void ldm_x4(uint32_t* r, uint32_t addr) {
    asm volatile("ldmatrix.sync.aligned.m8n8.x4.shared.b16 {%0,%1,%2,%3}, [%4];"
                 : "=r"(r[0]), "=r"(r[1]), "=r"(r[2]), "=r"(r[3]) : "r"(addr));
}
__device__ __forceinline__ void mma_bf16(float* c, const uint32_t* a, const uint32_t* b) {
    asm volatile(
        "mma.sync.aligned.m16n8k16.row.col.f32.bf16.bf16.f32 "
        "{%0,%1,%2,%3}, {%4,%5,%6,%7}, {%8,%9}, {%0,%1,%2,%3};"
        : "+f"(c[0]), "+f"(c[1]), "+f"(c[2]), "+f"(c[3])
        : "r"(a[0]), "r"(a[1]), "r"(a[2]), "r"(a[3]), "r"(b[0]), "r"(b[1]));
}
__device__ __forceinline__ void cp16(uint32_t dst, const void* src) {
    asm volatile("cp.async.cg.shared.global [%0], [%1], 16;"
                 :: "r"(dst), "l"(src) : "memory");
}

// ---------------- elementwise copy (float4) ----------------
__global__ void copy_kernel(const float4* __restrict__ src, float4* __restrict__ dst, int n4) {
    int i = blockIdx.x * blockDim.x + threadIdx.x;
    if (i < n4) dst[i] = src[i];
}

// ---------------- layernorm: one WARP per row; emits split-bf16 --------------
__global__ void ln_kernel(const float* __restrict__ x, const float* __restrict__ g,
                          const float* __restrict__ b,
                          __nv_bfloat16* __restrict__ oh, __nv_bfloat16* __restrict__ ol) {
    int row  = (blockIdx.x * blockDim.x + threadIdx.x) >> 5;
    int lane = threadIdx.x & 31;
    const float* xp = x + (size_t)row * DD;
    float4 a = *(const float4*)&xp[lane * 4];
    float4 c = *(const float4*)&xp[128 + lane * 4];
    float s = a.x + a.y + a.z + a.w + c.x + c.y + c.z + c.w;
    float mean = warpSum(s) * (1.0f / DD);
    float4 da = make_float4(a.x - mean, a.y - mean, a.z - mean, a.w - mean);
    float4 dc = make_float4(c.x - mean, c.y - mean, c.z - mean, c.w - mean);
    float v = da.x*da.x + da.y*da.y + da.z*da.z + da.w*da.w
            + dc.x*dc.x + dc.y*dc.y + dc.z*dc.z + dc.w*dc.w;
    float rs = rsqrtf(warpSum(v) * (1.0f / DD) + 1e-5f);
    float4 g0 = *(const float4*)&g[lane * 4];
    float4 g1 = *(const float4*)&g[128 + lane * 4];
    float4 b0 = *(const float4*)&b[lane * 4];
    float4 b1 = *(const float4*)&b[128 + lane * 4];
    float o0[4] = { da.x*rs*g0.x + b0.x, da.y*rs*g0.y + b0.y,
                    da.z*rs*g0.z + b0.z, da.w*rs*g0.w + b0.w };
    float o1[4] = { dc.x*rs*g1.x + b1.x, dc.y*rs*g1.y + b1.y,
                    dc.z*rs*g1.z + b1.z, dc.w*rs*g1.w + b1.w };
    size_t base = (size_t)row * DD;
    #pragma unroll
    for (int j = 0; j < 2; j++) {
        __nv_bfloat16 h0, l0, h1, l1;
        splitf(o0[j*2+0], h0, l0); splitf(o0[j*2+1], h1, l1);
        *(__nv_bfloat162*)&oh[base + lane*4 + j*2] = __halves2bfloat162(h0, h1);
        *(__nv_bfloat162*)&ol[base + lane*4 + j*2] = __halves2bfloat162(l0, l1);
        splitf(o1[j*2+0], h0, l0); splitf(o1[j*2+1], h1, l1);
        *(__nv_bfloat162*)&oh[base + 128 + lane*4 + j*2] = __halves2bfloat162(h0, h1);
        *(__nv_bfloat162*)&ol[base + 128 + lane*4 + j*2] = __halves2bfloat162(l0, l1);
    }
}

// ---------------- row sum-of-squares: one WARP per row of 256 ----------------
__global__ void rowsumsq_kernel(const float* __restrict__ x, float* __restrict__ out) {
    int row  = (blockIdx.x * blockDim.x + threadIdx.x) >> 5;
    int lane = threadIdx.x & 31;
    const float* xp = x + (size_t)row * DD;
    float4 a = *(const float4*)&xp[lane * 4];
    float4 c = *(const float4*)&xp[128 + lane * 4];
    float s = a.x*a.x + a.y*a.y + a.z*a.z + a.w*a.w
            + c.x*c.x + c.y*c.y + c.z*c.z + c.w*c.w;
    s = warpSum(s);
    if (lane == 0) out[row] = s;
}

// ---------------- weight transpose + bf16 split: W[K,N] -> out[N,K] ----------
__global__ void wsplit_kernel(const float* __restrict__ W,
                              __nv_bfloat16* __restrict__ oh, __nv_bfloat16* __restrict__ ol,
                              int K, int N) {
    __shared__ float tile[32][33];
    int k0 = blockIdx.y * 32, n0 = blockIdx.x * 32;
    int tx = threadIdx.x, ty = threadIdx.y;   // 32 x 8
    #pragma unroll
    for (int j = 0; j < 4; j++)
        tile[ty + j*8][tx] = W[(size_t)(k0 + ty + j*8) * N + n0 + tx];
    __syncthreads();
    #pragma unroll
    for (int j = 0; j < 4; j++) {
        int n = ty + j*8;
        float v = tile[tx][n];
        size_t idx = (size_t)(n0 + n) * K + k0 + tx;
        __nv_bfloat16 h, l; splitf(v, h, l);
        oh[idx] = h; ol[idx] = l;
    }
}

// ---------------- split-bf16 GEMM on HMMA (mma.sync) -------------------------
// C[M,N] = (Ahi+Alo) @ (Bhi+Blo)^T, A [M,K] row-major, Bt [N,K] row-major,
// fp32 accumulation, 3 products (hh, hl, lh). 128x128 CTA tile, BK=32,
// 8 warps (4m x 2n), warp tile 32x64 of m16n8k16 atoms. cp.async double buffer.
#define PADK   40                       // smem row stride (bf16) -> conflict-free ldmatrix
#define ARR_B  (128*PADK*2)             // bytes per operand array (10240)
#define OFF_AH 0
#define OFF_AL (1*ARR_B)
#define OFF_BH (2*ARR_B)
#define OFF_BL (3*ARR_B)
#define BUF_B  (4*ARR_B)                // 40960 bytes per buffer
#define GM_SMEM (2*BUF_B)               // 81920

__global__ __launch_bounds__(256)
void gemm_mma(const __nv_bfloat16* __restrict__ Ahi, const __nv_bfloat16* __restrict__ Alo,
              const __nv_bfloat16* __restrict__ Bhi, const __nv_bfloat16* __restrict__ Blo,
              const float* __restrict__ bias, const float* __restrict__ res,
              float* __restrict__ C,
              __nv_bfloat16* __restrict__ Chi, __nv_bfloat16* __restrict__ Clo,
              int M, int N, int K, int act) {
    extern __shared__ char smem[];
    const uint32_t sm = smem_u32(smem);
    const int m0 = blockIdx.y * 128;
    const int n0 = blockIdx.x * 128;
    const int t = threadIdx.x;
    const int wid = t >> 5, lid = t & 31;
    const int wm = wid & 3;              // 4 warps in m (32 rows each)
    const int wn = wid >> 2;             // 2 warps in n (64 cols each)
    const int NC = K >> 5;               // K chunks of 32

    float acc[2][8][4];
    #pragma unroll
    for (int i = 0; i < 2; i++)
        #pragma unroll
        for (int j = 0; j < 8; j++)
            #pragma unroll
            for (int q = 0; q < 4; q++) acc[i][j][q] = 0.f;

    auto issueChunk = [&](int c, int buf) {
        const int kb = c * 32;
        const uint32_t base = sm + buf * BUF_B;
        #pragma unroll
        for (int i = 0; i < 2; i++) {
            int idx = i * 256 + t;       // 0..511
            int r = idx >> 2, seg = idx & 3;
            uint32_t so = (uint32_t)(r * PADK + seg * 8) * 2;
            size_t ga = (size_t)(m0 + r) * K + kb + seg * 8;
            size_t gb = (size_t)(n0 + r) * K + kb + seg * 8;
            cp16(base + OFF_AH + so, &Ahi[ga]);
            cp16(base + OFF_AL + so, &Alo[ga]);
            cp16(base + OFF_BH + so, &Bhi[gb]);
            cp16(base + OFF_BL + so, &Blo[gb]);
        }
        asm volatile("cp.async.commit_group;" ::: "memory");
    };

    issueChunk(0, 0);

    for (int c = 0; c < NC; c++) {
        const int buf = c & 1;
        if (c + 1 < NC) {
            issueChunk(c + 1, buf ^ 1);
            asm volatile("cp.async.wait_group 1;" ::: "memory");
        } else {
            asm volatile("cp.async.wait_group 0;" ::: "memory");
        }
        __syncthreads();

        const uint32_t base = sm + buf * BUF_B;
        #pragma unroll
        for (int kk = 0; kk < 32; kk += 16) {
            // A fragments: 2 m-atoms x (hi,lo)
            uint32_t a_h[2][4], a_l[2][4];
            #pragma unroll
            for (int at = 0; at < 2; at++) {
                int row = wm * 32 + at * 16 + (lid & 15);
                int col = kk + (lid >> 4) * 8;
                uint32_t ro = (uint32_t)(row * PADK + col) * 2;
                ldm_x4(a_h[at], base + OFF_AH + ro);
                ldm_x4(a_l[at], base + OFF_AL + ro);
            }
            // B fragments: 8 n-atoms x (hi,lo); x4 loads 2 n-atoms at once
            uint32_t b_h[8][2], b_l[8][2];
            #pragma unroll
            for (int np = 0; np < 4; np++) {
                int quad = lid >> 3, qr = lid & 7;
                int nrow = wn * 64 + np * 16 + (quad >> 1) * 8 + qr;
                int col  = kk + (quad & 1) * 8;
                uint32_t ro = (uint32_t)(nrow * PADK + col) * 2;
                uint32_t r4[4];
                ldm_x4(r4, base + OFF_BH + ro);
                b_h[np*2][0] = r4[0]; b_h[np*2][1] = r4[1];
                b_h[np*2+1][0] = r4[2]; b_h[np*2+1][1] = r4[3];
                ldm_x4(r4, base + OFF_BL + ro);
                b_l[np*2][0] = r4[0]; b_l[np*2][1] = r4[1];
                b_l[np*2+1][0] = r4[2]; b_l[np*2+1][1] = r4[3];
            }
            // 3-product MMAs
            #pragma unroll
            for (int at = 0; at < 2; at++)
                #pragma unroll
                for (int nt = 0; nt < 8; nt++) {
                    mma_bf16(acc[at][nt], a_h[at], b_h[nt]);
                    mma_bf16(acc[at][nt], a_h[at], b_l[nt]);
                    mma_bf16(acc[at][nt], a_l[at], b_h[nt]);
                }
        }
        __syncthreads();
    }

    // ---- epilogue: direct register -> gmem ----
    #pragma unroll
    for (int at = 0; at < 2; at++) {
        #pragma unroll
        for (int nt = 0; nt < 8; nt++) {
            int col = n0 + wn * 64 + nt * 8 + (lid & 3) * 2;
            #pragma unroll
            for (int half = 0; half < 2; half++) {
                int row = m0 + wm * 32 + at * 16 + (lid >> 2) + half * 8;
                float v0 = acc[at][nt][half * 2 + 0];
                float v1 = acc[at][nt][half * 2 + 1];
                size_t gi = (size_t)row * N + col;
                if (bias) { v0 += bias[col]; v1 += bias[col + 1]; }
                if (act)  { v0 = gelu_f(v0); v1 = gelu_f(v1); }
                if (res)  { float2 r2 = *(const float2*)&res[gi]; v0 += r2.x; v1 += r2.y; }
                if (C) {
                    *(float2*)&C[gi] = make_float2(v0, v1);
                } else {
                    __nv_bfloat16 h0, l0, h1, l1;
                    splitf(v0, h0, l0); splitf(v1, h1, l1);
                    *(__nv_bfloat162*)&Chi[gi] = __halves2bfloat162(h0, h1);
                    *(__nv_bfloat162*)&Clo[gi] = __halves2bfloat162(l0, l1);
                }
            }
        }
    }
}

// ---------------- flash attention (fp32) — emits split-bf16 output -----------
__global__ __launch_bounds__(128)
void attn_kernel(const float* __restrict__ q, const float* __restrict__ kv,
                 __nv_bfloat16* __restrict__ oh, __nv_bfloat16* __restrict__ ol) {
    __shared__ float Ks[32][32];
    __shared__ float Vs[32][32];
    const int h = blockIdx.y, b = blockIdx.z;
    const int t = threadIdx.x;
    const int qrow = blockIdx.x * 128 + t;
    const float scale = 0.17677669529663687f;  // 1/sqrt(32)

    const float* qp = q + ((size_t)(b * NTOK) + qrow) * DD + h * DHEAD;
    float qr[32];
    #pragma unroll
    for (int i = 0; i < 8; i++) {
        float4 v = *(const float4*)&qp[i * 4];
        qr[i*4+0] = v.x * scale; qr[i*4+1] = v.y * scale;
        qr[i*4+2] = v.z * scale; qr[i*4+3] = v.w * scale;
    }
    float o[32];
    #pragma unroll
    for (int d = 0; d < 32; d++) o[d] = 0.f;
    float m = -1e30f, l = 0.f;

    for (int kt = 0; kt < NTOK; kt += 32) {
        const float* kb_ = kv + ((size_t)(b * NTOK) + kt) * (2 * DD) + h * DHEAD;
        #pragma unroll
        for (int i = 0; i < 2; i++) {
            int idx = i * 128 + t;
            int r = idx >> 3, c4 = (idx & 7) * 4;
            *(float4*)&Ks[r][c4] = *(const float4*)&kb_[(size_t)r * (2 * DD) + c4];
            *(float4*)&Vs[r][c4] = *(const float4*)&kb_[(size_t)r * (2 * DD) + DD + c4];
        }
        __syncthreads();

        float s[32];
        float tmax = -1e30f;
        #pragma unroll
        for (int j = 0; j < 32; j++) {
            const float4* kp = (const float4*)&Ks[j][0];
            float acc = 0.f;
            #pragma unroll
            for (int i2 = 0; i2 < 8; i2++) {
                float4 k4 = kp[i2];
                acc += qr[i2*4+0]*k4.x + qr[i2*4+1]*k4.y
                     + qr[i2*4+2]*k4.z + qr[i2*4+3]*k4.w;
            }
            s[j] = acc;
            tmax = fmaxf(tmax, acc);
        }
        float mnew = fmaxf(m, tmax);
        float corr = __expf(m - mnew);
        l *= corr;
        #pragma unroll
        for (int d = 0; d < 32; d++) o[d] *= corr;
        #pragma unroll
        for (int j = 0; j < 32; j++) {
            float p = __expf(s[j] - mnew);
            l += p;
            const float4* vp = (const float4*)&Vs[j][0];
            #pragma unroll
            for (int i2 = 0; i2 < 8; i2++) {
                float4 v4 = vp[i2];
                o[i2*4+0] += p * v4.x; o[i2*4+1] += p * v4.y;
                o[i2*4+2] += p * v4.z; o[i2*4+3] += p * v4.w;
            }
        }
        m = mnew;
        __syncthreads();
    }

    float inv = 1.f / l;
    size_t base = ((size_t)(b * NTOK) + qrow) * DD + h * DHEAD;
    #pragma unroll
    for (int i = 0; i < 16; i++) {
        __nv_bfloat16 h0, l0, h1, l1;
        splitf(o[2*i] * inv, h0, l0);
        splitf(o[2*i+1] * inv, h1, l1);
        *(__nv_bfloat162*)&oh[base + 2*i] = __halves2bfloat162(h0, h1);
        *(__nv_bfloat162*)&ol[base + 2*i] = __halves2bfloat162(l0, l1);
    }
}

// ---------------- kmeans ----------------
__global__ void initcent_kernel(const float* __restrict__ x, float* __restrict__ cent) {
    cent[(size_t)blockIdx.x * DD + threadIdx.x] = x[(size_t)blockIdx.x * DD + threadIdx.x];
}

__global__ __launch_bounds__(128)
void assign_kernel(const float* __restrict__ x, const float* __restrict__ cent,
                   const float* __restrict__ xsq, const float* __restrict__ csq,
                   int* __restrict__ lab) {
    __shared__ float Xs[128][33];
    __shared__ float Cs[64][32];
    const int t = threadIdx.x;
    const int p0 = blockIdx.x * 128;

    float dot[64];
    #pragma unroll
    for (int c = 0; c < 64; c++) dot[c] = 0.f;

    for (int dc = 0; dc < DD; dc += 32) {
        #pragma unroll
        for (int i = 0; i < 8; i++) {
            int idx = i * 128 + t;
            int r = idx >> 3, c4 = (idx & 7) * 4;
            float4 v = *(const float4*)&x[(size_t)(p0 + r) * DD + dc + c4];
            Xs[r][c4 + 0] = v.x; Xs[r][c4 + 1] = v.y;
            Xs[r][c4 + 2] = v.z; Xs[r][c4 + 3] = v.w;
        }
        #pragma unroll
        for (int i = 0; i < 4; i++) {
            int idx = i * 128 + t;
            int r = idx >> 3, c4 = (idx & 7) * 4;
            *(float4*)&Cs[r][c4] = *(const float4*)&cent[(size_t)r * DD + dc + c4];
        }
        __syncthreads();
        #pragma unroll 4
        for (int d = 0; d < 32; d++) {
            float xv = Xs[t][d];
            #pragma unroll
            for (int c = 0; c < 64; c++) dot[c] += xv * Cs[c][d];
        }
        __syncthreads();
    }

    float xs = xsq[p0 + t];
    float best = 3.4e38f;
    int bl = 0;
    #pragma unroll
    for (int c = 0; c < 64; c++) {
        float dd = xs - 2.f * dot[c] + csq[c];
        if (dd < best) { best = dd; bl = c; }
    }
    lab[p0 + t] = bl;
}

__global__ __launch_bounds__(256)
void segsum1_kernel(const float* __restrict__ x, const int* __restrict__ lab,
                    float* __restrict__ part, float* __restrict__ pcnt) {
    const int blk = blockIdx.x;
    const int c0  = blockIdx.y * 32;
    const int t = threadIdx.x;
    __shared__ float ps[32][DD];
    __shared__ int labs[128];
    #pragma unroll
    for (int i = 0; i < 32; i++) ps[i][t] = 0.f;
    if (t < 128) labs[t] = lab[blk * 128 + t];
    __syncthreads();
    const int p0 = blk * 128;
    for (int i = 0; i < 128; i++) {
        int l = labs[i] - c0;
        if ((unsigned)l < 32u)
            ps[l][t] += x[(size_t)(p0 + i) * DD + t];
    }
    for (int c = 0; c < 32; c++)
        part[((size_t)blk * KC + c0 + c) * DD + t] = ps[c][t];
    if (t < 32) {
        int cnt = 0;
        for (int i = 0; i < 128; i++) cnt += (labs[i] == c0 + t);
        pcnt[blk * KC + c0 + t] = (float)cnt;
    }
}

__global__ void segsum2_kernel(const float* __restrict__ part, const float* __restrict__ pcnt,
                               float* __restrict__ sums, float* __restrict__ cnts) {
    const int c = blockIdx.x, t = threadIdx.x;
    float acc = 0.f;
    for (int b2 = 0; b2 < SB; b2++) acc += part[((size_t)b2 * KC + c) * DD + t];
    sums[(size_t)c * DD + t] = acc;
    if (t == 0) {
        float cc = 0.f;
        for (int b2 = 0; b2 < SB; b2++) cc += pcnt[b2 * KC + c];
        cnts[c] = cc;
    }
}

__global__ void update_kernel(float* __restrict__ cent, const float* __restrict__ sums,
                              const float* __restrict__ cnts) {
    int c = blockIdx.x, t = threadIdx.x;
    float cnt = cnts[c];
    if (cnt > 0.f) cent[(size_t)c * DD + t] = sums[(size_t)c * DD + t] / fmaxf(cnt, 1.f);
}

__global__ void cproj_kernel(const float* __restrict__ cent, const float* __restrict__ kW,
                             const float* __restrict__ kb, float* __restrict__ cpro) {
    __shared__ float cr[DD];
    int c = blockIdx.x, t = threadIdx.x;
    cr[t] = cent[(size_t)c * DD + t];
    __syncthreads();
    float acc = kb[t];
    for (int d = 0; d < DD; d++) acc += cr[d] * kW[(size_t)d * DD + t];
    cpro[(size_t)c * DD + t] = acc;
}

__global__ void gather_kernel(const float* __restrict__ cproj, const int* __restrict__ lab,
                              float* __restrict__ out) {
    int p = blockIdx.x, t = threadIdx.x;
    out[(size_t)p * DD + t] = cproj[(size_t)lab[p] * DD + t];
}

// ---------------- host orchestration ----------------
extern "C" void kernel_launch(void* const* d_in, const int* in_sizes, int n_in,
                              void* d_out, int out_size) {
    const float* x_in = (const float*)d_in[0];
    const float* ln1g = (const float*)d_in[1];
    const float* ln1b = (const float*)d_in[2];
    const float* Wq   = (const float*)d_in[3];
    const float* Wkv  = (const float*)d_in[4];
    const float* Wo   = (const float*)d_in[5];
    const float* bo   = (const float*)d_in[6];
    const float* ln2g = (const float*)d_in[7];
    const float* ln2b = (const float*)d_in[8];
    const float* W1   = (const float*)d_in[9];
    const float* b1   = (const float*)d_in[10];
    const float* W2   = (const float*)d_in[11];
    const float* b2   = (const float*)d_in[12];
    const float* kW   = (const float*)d_in[13];
    const float* kb   = (const float*)d_in[14];
    float* out = (float*)d_out;

    float *p_x, *p_q, *p_kv, *p_xsq, *p_cent, *p_csq, *p_csum, *p_ccnt, *p_cpro, *p_part, *p_pcnt;
    __nv_bfloat16 *p_xnh, *p_xnl, *p_aoh, *p_aol, *p_hh, *p_hl, *p_wth, *p_wtl;
    int *p_lab;
    cudaGetSymbolAddress((void**)&p_x,    g_x);
    cudaGetSymbolAddress((void**)&p_q,    g_q);
    cudaGetSymbolAddress((void**)&p_kv,   g_kv);
    cudaGetSymbolAddress((void**)&p_xnh,  g_xnh);
    cudaGetSymbolAddress((void**)&p_xnl,  g_xnl);
    cudaGetSymbolAddress((void**)&p_aoh,  g_aoh);
    cudaGetSymbolAddress((void**)&p_aol,  g_aol);
    cudaGetSymbolAddress((void**)&p_hh,   g_hh);
    cudaGetSymbolAddress((void**)&p_hl,   g_hl);
    cudaGetSymbolAddress((void**)&p_wth,  g_wth);
    cudaGetSymbolAddress((void**)&p_wtl,  g_wtl);
    cudaGetSymbolAddress((void**)&p_xsq,  g_xsq);
    cudaGetSymbolAddress((void**)&p_cent, g_cent);
    cudaGetSymbolAddress((void**)&p_csq,  g_csq);
    cudaGetSymbolAddress((void**)&p_csum, g_csum);
    cudaGetSymbolAddress((void**)&p_ccnt, g_ccnt);
    cudaGetSymbolAddress((void**)&p_lab,  g_lab);
    cudaGetSymbolAddress((void**)&p_cpro, g_cpro);
    cudaGetSymbolAddress((void**)&p_part, g_part);
    cudaGetSymbolAddress((void**)&p_pcnt, g_pcnt);

    cudaFuncSetAttribute(gemm_mma, cudaFuncAttributeMaxDynamicSharedMemorySize, GM_SMEM);

    // x -> residual stream
    copy_kernel<<<(NT * DD / 4 + 255) / 256, 256>>>((const float4*)x_in, (float4*)p_x, NT * DD / 4);

    // transpose + split all weights
    dim3 tb32(32, 8);
    for (int l = 0; l < LL; l++) {
        size_t base = (size_t)l * WT_LAYER;
        wsplit_kernel<<<dim3(256/32, 256/32), tb32>>>(Wq  + (size_t)l*DD*DD,   p_wth + base + WQ_OFF,  p_wtl + base + WQ_OFF,  256, 256);
        wsplit_kernel<<<dim3(512/32, 256/32), tb32>>>(Wkv + (size_t)l*DD*2*DD, p_wth + base + WKV_OFF, p_wtl + base + WKV_OFF, 256, 512);
        wsplit_kernel<<<dim3(256/32, 256/32), tb32>>>(Wo  + (size_t)l*DD*DD,   p_wth + base + WO_OFF,  p_wtl + base + WO_OFF,  256, 256);
        wsplit_kernel<<<dim3(1024/32, 256/32), tb32>>>(W1 + (size_t)l*DD*MFF,  p_wth + base + W1_OFF,  p_wtl + base + W1_OFF,  256, 1024);
        wsplit_kernel<<<dim3(256/32, 1024/32), tb32>>>(W2 + (size_t)l*MFF*DD,  p_wth + base + W2_OFF,  p_wtl + base + W2_OFF,  1024, 256);
    }

    for (int l = 0; l < LL; l++) {
        size_t wb = (size_t)l * WT_LAYER;
        const __nv_bfloat16* wqh  = p_wth + wb + WQ_OFF,  *wql  = p_wtl + wb + WQ_OFF;
        const __nv_bfloat16* wkvh = p_wth + wb + WKV_OFF, *wkvl = p_wtl + wb + WKV_OFF;
        const __nv_bfloat16* woh  = p_wth + wb + WO_OFF,  *wol  = p_wtl + wb + WO_OFF;
        const __nv_bfloat16* w1h  = p_wth + wb + W1_OFF,  *w1l  = p_wtl + wb + W1_OFF;
        const __nv_bfloat16* w2h  = p_wth + wb + W2_OFF,  *w2l  = p_wtl + wb + W2_OFF;

        // ln1 -> split xn
        ln_kernel<<<NT / 8, 256>>>(p_x, ln1g + l * DD, ln1b + l * DD, p_xnh, p_xnl);
        // q: [8192,256]
        gemm_mma<<<dim3(2, 64), 256, GM_SMEM>>>(p_xnh, p_xnl, wqh, wql,
            nullptr, nullptr, p_q, nullptr, nullptr, NT, DD, DD, 0);
        // kv: [8192,512]
        gemm_mma<<<dim3(4, 64), 256, GM_SMEM>>>(p_xnh, p_xnl, wkvh, wkvl,
            nullptr, nullptr, p_kv, nullptr, nullptr, NT, 2 * DD, DD, 0);
        // attention -> split ao
        attn_kernel<<<dim3(NTOK / 128, HH, BB), 128>>>(p_q, p_kv, p_aoh, p_aol);
        // out proj + bias + residual (into x)
        gemm_mma<<<dim3(2, 64), 256, GM_SMEM>>>(p_aoh, p_aol, woh, wol,
            bo + l * DD, p_x, p_x, nullptr, nullptr, NT, DD, DD, 0);
        // ln2 -> split xn
        ln_kernel<<<NT / 8, 256>>>(p_x, ln2g + l * DD, ln2b + l * DD, p_xnh, p_xnl);
        // ffn up + gelu -> split h
        gemm_mma<<<dim3(8, 64), 256, GM_SMEM>>>(p_xnh, p_xnl, w1h, w1l,
            b1 + l * MFF, nullptr, nullptr, p_hh, p_hl, NT, MFF, DD, 1);
        // ffn down + bias + residual (into x)
        gemm_mma<<<dim3(2, 64), 256, GM_SMEM>>>(p_hh, p_hl, w2h, w2l,
            b2 + l * DD, p_x, p_x, nullptr, nullptr, NT, DD, MFF, 0);
    }

    // ---- kmeans (fp32, deterministic) ----
    initcent_kernel<<<KC, 256>>>(p_x, p_cent);
    rowsumsq_kernel<<<NT / 8, 256>>>(p_x, p_xsq);

    for (int it = 0; it < KM_IT; it++) {
        rowsumsq_kernel<<<KC / 8, 256>>>(p_cent, p_csq);
        assign_kernel<<<NT / 128, 128>>>(p_x, p_cent, p_xsq, p_csq, p_lab);
        segsum1_kernel<<<dim3(SB, 2), 256>>>(p_x, p_lab, p_part, p_pcnt);
        segsum2_kernel<<<KC, 256>>>(p_part, p_pcnt, p_csum, p_ccnt);
        update_kernel<<<KC, 256>>>(p_cent, p_csum, p_ccnt);
    }
    rowsumsq_kernel<<<KC / 8, 256>>>(p_cent, p_csq);
    assign_kernel<<<NT / 128, 128>>>(p_x, p_cent, p_xsq, p_csq, p_lab);

    cproj_kernel<<<KC, 256>>>(p_cent, kW, kb, p_cpro);
    gather_kernel<<<NT, 256>>>(p_cpro, p_lab, out);
}

// round 6
// speedup vs baseline: 2.9080x; 1.5811x over previous
#include <cuda_runtime.h>
#include <cuda_bf16.h>
#include <math.h>
#include <stdint.h>

// ---------------- problem constants ----------------
#define BB     8
#define NTOK   1024
#define DD     256
#define LL     4
#define MFF    1024
#define HH     8
#define DHEAD  32
#define NT     (BB*NTOK)      // 8192 tokens
#define KC     64             // clusters
#define KM_IT  10
#define SB     64             // segsum point-blocks (128 points each)

// weight-transpose scratch offsets (elements, per layer base = l*786432)
#define WT_LAYER 786432
#define WQ_OFF   0
#define WKV_OFF  65536
#define WO_OFF   196608
#define W1_OFF   262144
#define W2_OFF   524288

// ---------------- scratch (static device globals; no allocation allowed) ----
__device__ float g_x   [NT*DD];        // running residual stream (fp32)
__device__ __nv_bfloat16 g_qh [NT*DD];   // q projection hi
__device__ __nv_bfloat16 g_ql [NT*DD];   // q projection lo
__device__ __nv_bfloat16 g_kvh[NT*2*DD]; // k|v hi
__device__ __nv_bfloat16 g_kvl[NT*2*DD]; // k|v lo
__device__ __nv_bfloat16 g_xnh[NT*DD]; // layernorm out hi
__device__ __nv_bfloat16 g_xnl[NT*DD]; // layernorm out lo
__device__ __nv_bfloat16 g_aoh[NT*DD]; // attention out hi
__device__ __nv_bfloat16 g_aol[NT*DD]; // attention out lo
__device__ __nv_bfloat16 g_hh [NT*MFF];// ffn hidden hi
__device__ __nv_bfloat16 g_hl [NT*MFF];// ffn hidden lo
__device__ __nv_bfloat16 g_wth[LL*WT_LAYER]; // transposed weights hi
__device__ __nv_bfloat16 g_wtl[LL*WT_LAYER]; // transposed weights lo
__device__ float g_xsq [NT];
__device__ float g_cent[KC*DD];
__device__ float g_csq [KC];
__device__ float g_csum[KC*DD];
__device__ float g_ccnt[KC];
__device__ int   g_lab [NT];
__device__ float g_cpro[KC*DD];
__device__ float g_part[SB*KC*DD];
__device__ float g_pcnt[SB*KC];

// ---------------- small helpers ----------------
__device__ __forceinline__ float gelu_f(float x) {
    return 0.5f * x * (1.0f + erff(x * 0.7071067811865476f));
}
__device__ __forceinline__ float warpSum(float v) {
    #pragma unroll
    for (int o = 16; o > 0; o >>= 1) v += __shfl_xor_sync(0xffffffffu, v, o);
    return v;
}
__device__ __forceinline__ void splitf(float v, __nv_bfloat16& h, __nv_bfloat16& l) {
    h = __float2bfloat16(v);
    l = __float2bfloat16(v - __bfloat162float(h));
}
// pack two floats into (hi, lo) split bf16x2 register pairs
__device__ __forceinline__ void pack_split(float a, float b, uint32_t& hi, uint32_t& lo) {
    __nv_bfloat16 ah, al, bh, bl;
    splitf(a, ah, al); splitf(b, bh, bl);
    __nv_bfloat162 h2 = __halves2bfloat162(ah, bh);
    __nv_bfloat162 l2 = __halves2bfloat162(al, bl);
    hi = *(uint32_t*)&h2; lo = *(uint32_t*)&l2;
}
__device__ __forceinline__ uint32_t smem_u32(const void* p) {
    uint32_t a;
    asm("{ .reg .u64 t; cvta.to.shared.u64 t, %1; cvt.u32.u64 %0, t; }" : "=r"(a) : "l"(p));
    return a;
}

// ---------------- mma.sync helpers (sm_80+ path; valid on sm_103 base) ------
__device__ __forceinline__ void ldm_x4(uint32_t* r, uint32_t addr) {
    asm volatile("ldmatrix.sync.aligned.m8n8.x4.shared.b16 {%0,%1,%2,%3}, [%4];"
                 : "=r"(r[0]), "=r"(r[1]), "=r"(r[2]), "=r"(r[3]) : "r"(addr));
}
__device__ __forceinline__ void mma_bf16(float* c, const uint32_t* a, const uint32_t* b) {
    asm volatile(
        "mma.sync.aligned.m16n8k16.row.col.f32.bf16.bf16.f32 "
        "{%0,%1,%2,%3}, {%4,%5,%6,%7}, {%8,%9}, {%0,%1,%2,%3};"
        : "+f"(c[0]), "+f"(c[1]), "+f"(c[2]), "+f"(c[3])
        : "r"(a[0]), "r"(a[1]), "r"(a[2]), "r"(a[3]), "r"(b[0]), "r"(b[1]));
}
__device__ __forceinline__ void cp16(uint32_t dst, const void* src) {
    asm volatile("cp.async.cg.shared.global [%0], [%1], 16;"
                 :: "r"(dst), "l"(src) : "memory");
}

// ---------------- elementwise copy (float4) ----------------
__global__ void copy_kernel(const float4* __restrict__ src, float4* __restrict__ dst, int n4) {
    int i = blockIdx.x * blockDim.x + threadIdx.x;
    if (i < n4) dst[i] = src[i];
}

// ---------------- layernorm: one WARP per row; emits split-bf16 --------------
__global__ void ln_kernel(const float* __restrict__ x, const float* __restrict__ g,
                          const float* __restrict__ b,
                          __nv_bfloat16* __restrict__ oh, __nv_bfloat16* __restrict__ ol) {
    int row  = (blockIdx.x * blockDim.x + threadIdx.x) >> 5;
    int lane = threadIdx.x & 31;
    const float* xp = x + (size_t)row * DD;
    float4 a = *(const float4*)&xp[lane * 4];
    float4 c = *(const float4*)&xp[128 + lane * 4];
    float s = a.x + a.y + a.z + a.w + c.x + c.y + c.z + c.w;
    float mean = warpSum(s) * (1.0f / DD);
    float4 da = make_float4(a.x - mean, a.y - mean, a.z - mean, a.w - mean);
    float4 dc = make_float4(c.x - mean, c.y - mean, c.z - mean, c.w - mean);
    float v = da.x*da.x + da.y*da.y + da.z*da.z + da.w*da.w
            + dc.x*dc.x + dc.y*dc.y + dc.z*dc.z + dc.w*dc.w;
    float rs = rsqrtf(warpSum(v) * (1.0f / DD) + 1e-5f);
    float4 g0 = *(const float4*)&g[lane * 4];
    float4 g1 = *(const float4*)&g[128 + lane * 4];
    float4 b0 = *(const float4*)&b[lane * 4];
    float4 b1 = *(const float4*)&b[128 + lane * 4];
    float o0[4] = { da.x*rs*g0.x + b0.x, da.y*rs*g0.y + b0.y,
                    da.z*rs*g0.z + b0.z, da.w*rs*g0.w + b0.w };
    float o1[4] = { dc.x*rs*g1.x + b1.x, dc.y*rs*g1.y + b1.y,
                    dc.z*rs*g1.z + b1.z, dc.w*rs*g1.w + b1.w };
    size_t base = (size_t)row * DD;
    #pragma unroll
    for (int j = 0; j < 2; j++) {
        uint32_t uh, ul;
        pack_split(o0[j*2+0], o0[j*2+1], uh, ul);
        *(uint32_t*)&oh[base + lane*4 + j*2] = uh;
        *(uint32_t*)&ol[base + lane*4 + j*2] = ul;
        pack_split(o1[j*2+0], o1[j*2+1], uh, ul);
        *(uint32_t*)&oh[base + 128 + lane*4 + j*2] = uh;
        *(uint32_t*)&ol[base + 128 + lane*4 + j*2] = ul;
    }
}

// ---------------- row sum-of-squares: one WARP per row of 256 ----------------
__global__ void rowsumsq_kernel(const float* __restrict__ x, float* __restrict__ out) {
    int row  = (blockIdx.x * blockDim.x + threadIdx.x) >> 5;
    int lane = threadIdx.x & 31;
    const float* xp = x + (size_t)row * DD;
    float4 a = *(const float4*)&xp[lane * 4];
    float4 c = *(const float4*)&xp[128 + lane * 4];
    float s = a.x*a.x + a.y*a.y + a.z*a.z + a.w*a.w
            + c.x*c.x + c.y*c.y + c.z*c.z + c.w*c.w;
    s = warpSum(s);
    if (lane == 0) out[row] = s;
}

// ---------------- weight transpose + bf16 split: W[K,N] -> out[N,K] ----------
__global__ void wsplit_kernel(const float* __restrict__ W,
                              __nv_bfloat16* __restrict__ oh, __nv_bfloat16* __restrict__ ol,
                              int K, int N) {
    __shared__ float tile[32][33];
    int k0 = blockIdx.y * 32, n0 = blockIdx.x * 32;
    int tx = threadIdx.x, ty = threadIdx.y;   // 32 x 8
    #pragma unroll
    for (int j = 0; j < 4; j++)
        tile[ty + j*8][tx] = W[(size_t)(k0 + ty + j*8) * N + n0 + tx];
    __syncthreads();
    #pragma unroll
    for (int j = 0; j < 4; j++) {
        int n = ty + j*8;
        float v = tile[tx][n];
        size_t idx = (size_t)(n0 + n) * K + k0 + tx;
        __nv_bfloat16 h, l; splitf(v, h, l);
        oh[idx] = h; ol[idx] = l;
    }
}

// ---------------- split-bf16 GEMM on HMMA (mma.sync) -------------------------
#define PADK   40                       // smem row stride (bf16) -> conflict-free ldmatrix
#define ARR_B  (128*PADK*2)             // bytes per operand array (10240)
#define OFF_AH 0
#define OFF_AL (1*ARR_B)
#define OFF_BH (2*ARR_B)
#define OFF_BL (3*ARR_B)
#define BUF_B  (4*ARR_B)                // 40960 bytes per buffer
#define GM_SMEM (2*BUF_B)               // 81920

__global__ __launch_bounds__(256)
void gemm_mma(const __nv_bfloat16* __restrict__ Ahi, const __nv_bfloat16* __restrict__ Alo,
              const __nv_bfloat16* __restrict__ Bhi, const __nv_bfloat16* __restrict__ Blo,
              const float* __restrict__ bias, const float* __restrict__ res,
              float* __restrict__ C,
              __nv_bfloat16* __restrict__ Chi, __nv_bfloat16* __restrict__ Clo,
              int M, int N, int K, int act) {
    extern __shared__ char smem[];
    const uint32_t sm = smem_u32(smem);
    const int m0 = blockIdx.y * 128;
    const int n0 = blockIdx.x * 128;
    const int t = threadIdx.x;
    const int wid = t >> 5, lid = t & 31;
    const int wm = wid & 3;              // 4 warps in m (32 rows each)
    const int wn = wid >> 2;             // 2 warps in n (64 cols each)
    const int NC = K >> 5;               // K chunks of 32

    float acc[2][8][4];
    #pragma unroll
    for (int i = 0; i < 2; i++)
        #pragma unroll
        for (int j = 0; j < 8; j++)
            #pragma unroll
            for (int q = 0; q < 4; q++) acc[i][j][q] = 0.f;

    auto issueChunk = [&](int c, int buf) {
        const int kb = c * 32;
        const uint32_t base = sm + buf * BUF_B;
        #pragma unroll
        for (int i = 0; i < 2; i++) {
            int idx = i * 256 + t;       // 0..511
            int r = idx >> 2, seg = idx & 3;
            uint32_t so = (uint32_t)(r * PADK + seg * 8) * 2;
            size_t ga = (size_t)(m0 + r) * K + kb + seg * 8;
            size_t gb = (size_t)(n0 + r) * K + kb + seg * 8;
            cp16(base + OFF_AH + so, &Ahi[ga]);
            cp16(base + OFF_AL + so, &Alo[ga]);
            cp16(base + OFF_BH + so, &Bhi[gb]);
            cp16(base + OFF_BL + so, &Blo[gb]);
        }
        asm volatile("cp.async.commit_group;" ::: "memory");
    };

    issueChunk(0, 0);

    for (int c = 0; c < NC; c++) {
        const int buf = c & 1;
        if (c + 1 < NC) {
            issueChunk(c + 1, buf ^ 1);
            asm volatile("cp.async.wait_group 1;" ::: "memory");
        } else {
            asm volatile("cp.async.wait_group 0;" ::: "memory");
        }
        __syncthreads();

        const uint32_t base = sm + buf * BUF_B;
        #pragma unroll
        for (int kk = 0; kk < 32; kk += 16) {
            uint32_t a_h[2][4], a_l[2][4];
            #pragma unroll
            for (int at = 0; at < 2; at++) {
                int row = wm * 32 + at * 16 + (lid & 15);
                int col = kk + (lid >> 4) * 8;
                uint32_t ro = (uint32_t)(row * PADK + col) * 2;
                ldm_x4(a_h[at], base + OFF_AH + ro);
                ldm_x4(a_l[at], base + OFF_AL + ro);
            }
            uint32_t b_h[8][2], b_l[8][2];
            #pragma unroll
            for (int np = 0; np < 4; np++) {
                int quad = lid >> 3, qr = lid & 7;
                int nrow = wn * 64 + np * 16 + (quad >> 1) * 8 + qr;
                int col  = kk + (quad & 1) * 8;
                uint32_t ro = (uint32_t)(nrow * PADK + col) * 2;
                uint32_t r4[4];
                ldm_x4(r4, base + OFF_BH + ro);
                b_h[np*2][0] = r4[0]; b_h[np*2][1] = r4[1];
                b_h[np*2+1][0] = r4[2]; b_h[np*2+1][1] = r4[3];
                ldm_x4(r4, base + OFF_BL + ro);
                b_l[np*2][0] = r4[0]; b_l[np*2][1] = r4[1];
                b_l[np*2+1][0] = r4[2]; b_l[np*2+1][1] = r4[3];
            }
            #pragma unroll
            for (int at = 0; at < 2; at++)
                #pragma unroll
                for (int nt = 0; nt < 8; nt++) {
                    mma_bf16(acc[at][nt], a_h[at], b_h[nt]);
                    mma_bf16(acc[at][nt], a_h[at], b_l[nt]);
                    mma_bf16(acc[at][nt], a_l[at], b_h[nt]);
                }
        }
        __syncthreads();
    }

    // ---- epilogue ----
    #pragma unroll
    for (int at = 0; at < 2; at++) {
        #pragma unroll
        for (int nt = 0; nt < 8; nt++) {
            int col = n0 + wn * 64 + nt * 8 + (lid & 3) * 2;
            #pragma unroll
            for (int half = 0; half < 2; half++) {
                int row = m0 + wm * 32 + at * 16 + (lid >> 2) + half * 8;
                float v0 = acc[at][nt][half * 2 + 0];
                float v1 = acc[at][nt][half * 2 + 1];
                size_t gi = (size_t)row * N + col;
                if (bias) { v0 += bias[col]; v1 += bias[col + 1]; }
                if (act)  { v0 = gelu_f(v0); v1 = gelu_f(v1); }
                if (res)  { float2 r2 = *(const float2*)&res[gi]; v0 += r2.x; v1 += r2.y; }
                if (C) {
                    *(float2*)&C[gi] = make_float2(v0, v1);
                } else {
                    uint32_t uh, ul;
                    pack_split(v0, v1, uh, ul);
                    *(uint32_t*)&Chi[gi] = uh;
                    *(uint32_t*)&Clo[gi] = ul;
                }
            }
        }
    }
}

// ---------------- tensor-core flash attention (split-bf16, 3-product) --------
// grid (8 qtiles of 128, HH, BB), 128 threads (4 warps x 32 q rows).
// K tiles of 64 keys. S=QK^T and P*V both on mma.m16n8k16 with hi/lo splits.
#define AQS 40     // Q/K smem row stride (bf16)
#define AVS 72     // V^T smem row stride (bf16)

__global__ __launch_bounds__(128)
void attn_mma(const __nv_bfloat16* __restrict__ qh, const __nv_bfloat16* __restrict__ ql,
              const __nv_bfloat16* __restrict__ kvh, const __nv_bfloat16* __restrict__ kvl,
              __nv_bfloat16* __restrict__ aoh, __nv_bfloat16* __restrict__ aol) {
    __shared__ __nv_bfloat16 Qh[128*AQS], Ql[128*AQS];
    __shared__ __nv_bfloat16 Kh[64*AQS],  Kl[64*AQS];
    __shared__ __nv_bfloat16 Vh[32*AVS],  Vl[32*AVS];
    const int h = blockIdx.y, b = blockIdx.z;
    const int t = threadIdx.x, w = t >> 5, lid = t & 31;
    const int q0 = blockIdx.x * 128;
    const int quad = lid >> 3, qr = lid & 7;
    const uint32_t sQh = smem_u32(Qh), sQl = smem_u32(Ql);
    const uint32_t sKh = smem_u32(Kh), sKl = smem_u32(Kl);
    const uint32_t sVh = smem_u32(Vh), sVl = smem_u32(Vl);
    const float scale = 0.17677669529663687f;   // 1/sqrt(32)

    // ---- stage Q tile (128 x 32) ----
    #pragma unroll
    for (int i = 0; i < 4; i++) {
        int idx = i * 128 + t; int r = idx >> 2, seg = idx & 3;
        size_t g = ((size_t)(b * NTOK) + q0 + r) * DD + h * DHEAD + seg * 8;
        *(uint4*)(Qh + r * AQS + seg * 8) = *(const uint4*)&qh[g];
        *(uint4*)(Ql + r * AQS + seg * 8) = *(const uint4*)&ql[g];
    }

    float O[2][4][4];
    #pragma unroll
    for (int a1 = 0; a1 < 2; a1++)
        #pragma unroll
        for (int a2 = 0; a2 < 4; a2++)
            #pragma unroll
            for (int a3 = 0; a3 < 4; a3++) O[a1][a2][a3] = 0.f;
    float mrow[2][2] = {{-1e30f,-1e30f},{-1e30f,-1e30f}};
    float lrow[2][2] = {{0.f,0.f},{0.f,0.f}};

    for (int kt = 0; kt < NTOK; kt += 64) {
        // K tile via cp.async (64 x 32 hi/lo)
        #pragma unroll
        for (int i = 0; i < 2; i++) {
            int idx = i * 128 + t; int r = idx >> 2, seg = idx & 3;
            size_t g = ((size_t)(b * NTOK) + kt + r) * (2 * DD) + h * DHEAD + seg * 8;
            cp16(sKh + (uint32_t)(r * AQS + seg * 8) * 2, &kvh[g]);
            cp16(sKl + (uint32_t)(r * AQS + seg * 8) * 2, &kvl[g]);
        }
        asm volatile("cp.async.commit_group;" ::: "memory");
        // V tile transposed: Vt[dim][key], thread handles key pair (2*r2, 2*r2+1), 8 dims
        {
            int r2 = lid, seg = w;    // r2 0..31, seg 0..3 -> dims seg*8..seg*8+7
            size_t g0 = ((size_t)(b * NTOK) + kt + 2 * r2) * (2 * DD) + DD + h * DHEAD + seg * 8;
            uint4 vh0 = *(const uint4*)&kvh[g0];
            uint4 vh1 = *(const uint4*)&kvh[g0 + 2 * DD];
            uint4 vl0 = *(const uint4*)&kvl[g0];
            uint4 vl1 = *(const uint4*)&kvl[g0 + 2 * DD];
            const __nv_bfloat16* h0 = (const __nv_bfloat16*)&vh0;
            const __nv_bfloat16* h1 = (const __nv_bfloat16*)&vh1;
            const __nv_bfloat16* l0 = (const __nv_bfloat16*)&vl0;
            const __nv_bfloat16* l1 = (const __nv_bfloat16*)&vl1;
            #pragma unroll
            for (int j = 0; j < 8; j++) {
                __nv_bfloat162 ph = __halves2bfloat162(h0[j], h1[j]);
                __nv_bfloat162 pl = __halves2bfloat162(l0[j], l1[j]);
                int off = (seg * 8 + j) * AVS + 2 * r2;
                *(uint32_t*)(Vh + off) = *(uint32_t*)&ph;
                *(uint32_t*)(Vl + off) = *(uint32_t*)&pl;
            }
        }
        asm volatile("cp.async.wait_group 0;" ::: "memory");
        __syncthreads();

        // ---- S = Q K^T (warp: 32 q rows x 64 keys), 3 products ----
        float S[2][8][4];
        #pragma unroll
        for (int a1 = 0; a1 < 2; a1++)
            #pragma unroll
            for (int a2 = 0; a2 < 8; a2++)
                #pragma unroll
                for (int a3 = 0; a3 < 4; a3++) S[a1][a2][a3] = 0.f;

        #pragma unroll
        for (int kk = 0; kk < 2; kk++) {
            uint32_t qa_h[2][4], qa_l[2][4];
            #pragma unroll
            for (int at = 0; at < 2; at++) {
                uint32_t ro = (uint32_t)((w * 32 + at * 16 + (lid & 15)) * AQS
                                         + kk * 16 + (lid >> 4) * 8) * 2;
                ldm_x4(qa_h[at], sQh + ro);
                ldm_x4(qa_l[at], sQl + ro);
            }
            uint32_t kb_h[8][2], kb_l[8][2];
            #pragma unroll
            for (int np = 0; np < 4; np++) {
                uint32_t ro = (uint32_t)((np * 16 + (quad >> 1) * 8 + qr) * AQS
                                         + kk * 16 + (quad & 1) * 8) * 2;
                uint32_t r4[4];
                ldm_x4(r4, sKh + ro);
                kb_h[np*2][0] = r4[0]; kb_h[np*2][1] = r4[1];
                kb_h[np*2+1][0] = r4[2]; kb_h[np*2+1][1] = r4[3];
                ldm_x4(r4, sKl + ro);
                kb_l[np*2][0] = r4[0]; kb_l[np*2][1] = r4[1];
                kb_l[np*2+1][0] = r4[2]; kb_l[np*2+1][1] = r4[3];
            }
            #pragma unroll
            for (int at = 0; at < 2; at++)
                #pragma unroll
                for (int nt = 0; nt < 8; nt++) {
                    mma_bf16(S[at][nt], qa_h[at], kb_h[nt]);
                    mma_bf16(S[at][nt], qa_h[at], kb_l[nt]);
                    mma_bf16(S[at][nt], qa_l[at], kb_h[nt]);
                }
        }

        // ---- online softmax + P*V per m-atom ----
        #pragma unroll
        for (int at = 0; at < 2; at++) {
            float tm0 = -1e30f, tm1 = -1e30f;
            #pragma unroll
            for (int nt = 0; nt < 8; nt++) {
                S[at][nt][0] *= scale; S[at][nt][1] *= scale;
                S[at][nt][2] *= scale; S[at][nt][3] *= scale;
                tm0 = fmaxf(tm0, fmaxf(S[at][nt][0], S[at][nt][1]));
                tm1 = fmaxf(tm1, fmaxf(S[at][nt][2], S[at][nt][3]));
            }
            tm0 = fmaxf(tm0, __shfl_xor_sync(0xffffffffu, tm0, 1));
            tm0 = fmaxf(tm0, __shfl_xor_sync(0xffffffffu, tm0, 2));
            tm1 = fmaxf(tm1, __shfl_xor_sync(0xffffffffu, tm1, 1));
            tm1 = fmaxf(tm1, __shfl_xor_sync(0xffffffffu, tm1, 2));
            float m0n = fmaxf(mrow[at][0], tm0);
            float m1n = fmaxf(mrow[at][1], tm1);
            float c0 = __expf(mrow[at][0] - m0n);
            float c1 = __expf(mrow[at][1] - m1n);
            mrow[at][0] = m0n; mrow[at][1] = m1n;

            float ls0 = 0.f, ls1 = 0.f;
            uint32_t pah[4][4], pal[4][4];
            #pragma unroll
            for (int g = 0; g < 4; g++) {
                float p00 = __expf(S[at][2*g  ][0] - m0n);
                float p01 = __expf(S[at][2*g  ][1] - m0n);
                float p02 = __expf(S[at][2*g  ][2] - m1n);
                float p03 = __expf(S[at][2*g  ][3] - m1n);
                float p10 = __expf(S[at][2*g+1][0] - m0n);
                float p11 = __expf(S[at][2*g+1][1] - m0n);
                float p12 = __expf(S[at][2*g+1][2] - m1n);
                float p13 = __expf(S[at][2*g+1][3] - m1n);
                ls0 += p00 + p01 + p10 + p11;
                ls1 += p02 + p03 + p12 + p13;
                pack_split(p00, p01, pah[g][0], pal[g][0]);
                pack_split(p02, p03, pah[g][1], pal[g][1]);
                pack_split(p10, p11, pah[g][2], pal[g][2]);
                pack_split(p12, p13, pah[g][3], pal[g][3]);
            }
            ls0 += __shfl_xor_sync(0xffffffffu, ls0, 1);
            ls0 += __shfl_xor_sync(0xffffffffu, ls0, 2);
            ls1 += __shfl_xor_sync(0xffffffffu, ls1, 1);
            ls1 += __shfl_xor_sync(0xffffffffu, ls1, 2);
            lrow[at][0] = lrow[at][0] * c0 + ls0;
            lrow[at][1] = lrow[at][1] * c1 + ls1;
            #pragma unroll
            for (int vn = 0; vn < 4; vn++) {
                O[at][vn][0] *= c0; O[at][vn][1] *= c0;
                O[at][vn][2] *= c1; O[at][vn][3] *= c1;
            }
            // P * V over 4 key-groups of 16
            #pragma unroll
            for (int g = 0; g < 4; g++) {
                uint32_t vb_h[4][2], vb_l[4][2];
                #pragma unroll
                for (int np = 0; np < 2; np++) {
                    uint32_t ro = (uint32_t)((np * 16 + (quad >> 1) * 8 + qr) * AVS
                                             + g * 16 + (quad & 1) * 8) * 2;
                    uint32_t r4[4];
                    ldm_x4(r4, sVh + ro);
                    vb_h[np*2][0] = r4[0]; vb_h[np*2][1] = r4[1];
                    vb_h[np*2+1][0] = r4[2]; vb_h[np*2+1][1] = r4[3];
                    ldm_x4(r4, sVl + ro);
                    vb_l[np*2][0] = r4[0]; vb_l[np*2][1] = r4[1];
                    vb_l[np*2+1][0] = r4[2]; vb_l[np*2+1][1] = r4[3];
                }
                #pragma unroll
                for (int vn = 0; vn < 4; vn++) {
                    mma_bf16(O[at][vn], pah[g], vb_h[vn]);
                    mma_bf16(O[at][vn], pah[g], vb_l[vn]);
                    mma_bf16(O[at][vn], pal[g], vb_h[vn]);
                }
            }
        }
        __syncthreads();
    }

    // ---- normalize + write split-bf16 output ----
    #pragma unroll
    for (int at = 0; at < 2; at++) {
        float i0 = 1.f / lrow[at][0];
        float i1 = 1.f / lrow[at][1];
        int r0 = q0 + w * 32 + at * 16 + (lid >> 2);
        #pragma unroll
        for (int vn = 0; vn < 4; vn++) {
            int col = h * DHEAD + vn * 8 + (lid & 3) * 2;
            size_t g0 = ((size_t)(b * NTOK) + r0) * DD + col;
            size_t g1 = g0 + (size_t)8 * DD;
            uint32_t uh, ul;
            pack_split(O[at][vn][0] * i0, O[at][vn][1] * i0, uh, ul);
            *(uint32_t*)&aoh[g0] = uh; *(uint32_t*)&aol[g0] = ul;
            pack_split(O[at][vn][2] * i1, O[at][vn][3] * i1, uh, ul);
            *(uint32_t*)&aoh[g1] = uh; *(uint32_t*)&aol[g1] = ul;
        }
    }
}

// ---------------- kmeans ----------------
__global__ void initcent_kernel(const float* __restrict__ x, float* __restrict__ cent) {
    cent[(size_t)blockIdx.x * DD + threadIdx.x] = x[(size_t)blockIdx.x * DD + threadIdx.x];
}

__global__ __launch_bounds__(128)
void assign_kernel(const float* __restrict__ x, const float* __restrict__ cent,
                   const float* __restrict__ xsq, const float* __restrict__ csq,
                   int* __restrict__ lab) {
    __shared__ float Xs[128][33];
    __shared__ float Cs[64][32];
    const int t = threadIdx.x;
    const int p0 = blockIdx.x * 128;

    float dot[64];
    #pragma unroll
    for (int c = 0; c < 64; c++) dot[c] = 0.f;

    for (int dc = 0; dc < DD; dc += 32) {
        #pragma unroll
        for (int i = 0; i < 8; i++) {
            int idx = i * 128 + t;
            int r = idx >> 3, c4 = (idx & 7) * 4;
            float4 v = *(const float4*)&x[(size_t)(p0 + r) * DD + dc + c4];
            Xs[r][c4 + 0] = v.x; Xs[r][c4 + 1] = v.y;
            Xs[r][c4 + 2] = v.z; Xs[r][c4 + 3] = v.w;
        }
        #pragma unroll
        for (int i = 0; i < 4; i++) {
            int idx = i * 128 + t;
            int r = idx >> 3, c4 = (idx & 7) * 4;
            *(float4*)&Cs[r][c4] = *(const float4*)&cent[(size_t)r * DD + dc + c4];
        }
        __syncthreads();
        #pragma unroll 4
        for (int d = 0; d < 32; d++) {
            float xv = Xs[t][d];
            #pragma unroll
            for (int c = 0; c < 64; c++) dot[c] += xv * Cs[c][d];
        }
        __syncthreads();
    }

    float xs = xsq[p0 + t];
    float best = 3.4e38f;
    int bl = 0;
    #pragma unroll
    for (int c = 0; c < 64; c++) {
        float dd = xs - 2.f * dot[c] + csq[c];
        if (dd < best) { best = dd; bl = c; }
    }
    lab[p0 + t] = bl;
}

__global__ __launch_bounds__(256)
void segsum1_kernel(const float* __restrict__ x, const int* __restrict__ lab,
                    float* __restrict__ part, float* __restrict__ pcnt) {
    const int blk = blockIdx.x;
    const int c0  = blockIdx.y * 32;
    const int t = threadIdx.x;
    __shared__ float ps[32][DD];
    __shared__ int labs[128];
    #pragma unroll
    for (int i = 0; i < 32; i++) ps[i][t] = 0.f;
    if (t < 128) labs[t] = lab[blk * 128 + t];
    __syncthreads();
    const int p0 = blk * 128;
    for (int i = 0; i < 128; i++) {
        int l = labs[i] - c0;
        if ((unsigned)l < 32u)
            ps[l][t] += x[(size_t)(p0 + i) * DD + t];
    }
    for (int c = 0; c < 32; c++)
        part[((size_t)blk * KC + c0 + c) * DD + t] = ps[c][t];
    if (t < 32) {
        int cnt = 0;
        for (int i = 0; i < 128; i++) cnt += (labs[i] == c0 + t);
        pcnt[blk * KC + c0 + t] = (float)cnt;
    }
}

__global__ void segsum2_kernel(const float* __restrict__ part, const float* __restrict__ pcnt,
                               float* __restrict__ sums, float* __restrict__ cnts) {
    const int c = blockIdx.x, t = threadIdx.x;
    float acc = 0.f;
    for (int b2 = 0; b2 < SB; b2++) acc += part[((size_t)b2 * KC + c) * DD + t];
    sums[(size_t)c * DD + t] = acc;
    if (t == 0) {
        float cc = 0.f;
        for (int b2 = 0; b2 < SB; b2++) cc += pcnt[b2 * KC + c];
        cnts[c] = cc;
    }
}

__global__ void update_kernel(float* __restrict__ cent, const float* __restrict__ sums,
                              const float* __restrict__ cnts) {
    int c = blockIdx.x, t = threadIdx.x;
    float cnt = cnts[c];
    if (cnt > 0.f) cent[(size_t)c * DD + t] = sums[(size_t)c * DD + t] / fmaxf(cnt, 1.f);
}

__global__ void cproj_kernel(const float* __restrict__ cent, const float* __restrict__ kW,
                             const float* __restrict__ kb, float* __restrict__ cpro) {
    __shared__ float cr[DD];
    int c = blockIdx.x, t = threadIdx.x;
    cr[t] = cent[(size_t)c * DD + t];
    __syncthreads();
    float acc = kb[t];
    for (int d = 0; d < DD; d++) acc += cr[d] * kW[(size_t)d * DD + t];
    cpro[(size_t)c * DD + t] = acc;
}

__global__ void gather_kernel(const float* __restrict__ cproj, const int* __restrict__ lab,
                              float* __restrict__ out) {
    int p = blockIdx.x, t = threadIdx.x;
    out[(size_t)p * DD + t] = cproj[(size_t)lab[p] * DD + t];
}

// ---------------- host orchestration ----------------
extern "C" void kernel_launch(void* const* d_in, const int* in_sizes, int n_in,
                              void* d_out, int out_size) {
    const float* x_in = (const float*)d_in[0];
    const float* ln1g = (const float*)d_in[1];
    const float* ln1b = (const float*)d_in[2];
    const float* Wq   = (const float*)d_in[3];
    const float* Wkv  = (const float*)d_in[4];
    const float* Wo   = (const float*)d_in[5];
    const float* bo   = (const float*)d_in[6];
    const float* ln2g = (const float*)d_in[7];
    const float* ln2b = (const float*)d_in[8];
    const float* W1   = (const float*)d_in[9];
    const float* b1   = (const float*)d_in[10];
    const float* W2   = (const float*)d_in[11];
    const float* b2   = (const float*)d_in[12];
    const float* kW   = (const float*)d_in[13];
    const float* kb   = (const float*)d_in[14];
    float* out = (float*)d_out;

    float *p_x, *p_xsq, *p_cent, *p_csq, *p_csum, *p_ccnt, *p_cpro, *p_part, *p_pcnt;
    __nv_bfloat16 *p_qh, *p_ql, *p_kvh, *p_kvl;
    __nv_bfloat16 *p_xnh, *p_xnl, *p_aoh, *p_aol, *p_hh, *p_hl, *p_wth, *p_wtl;
    int *p_lab;
    cudaGetSymbolAddress((void**)&p_x,    g_x);
    cudaGetSymbolAddress((void**)&p_qh,   g_qh);
    cudaGetSymbolAddress((void**)&p_ql,   g_ql);
    cudaGetSymbolAddress((void**)&p_kvh,  g_kvh);
    cudaGetSymbolAddress((void**)&p_kvl,  g_kvl);
    cudaGetSymbolAddress((void**)&p_xnh,  g_xnh);
    cudaGetSymbolAddress((void**)&p_xnl,  g_xnl);
    cudaGetSymbolAddress((void**)&p_aoh,  g_aoh);
    cudaGetSymbolAddress((void**)&p_aol,  g_aol);
    cudaGetSymbolAddress((void**)&p_hh,   g_hh);
    cudaGetSymbolAddress((void**)&p_hl,   g_hl);
    cudaGetSymbolAddress((void**)&p_wth,  g_wth);
    cudaGetSymbolAddress((void**)&p_wtl,  g_wtl);
    cudaGetSymbolAddress((void**)&p_xsq,  g_xsq);
    cudaGetSymbolAddress((void**)&p_cent, g_cent);
    cudaGetSymbolAddress((void**)&p_csq,  g_csq);
    cudaGetSymbolAddress((void**)&p_csum, g_csum);
    cudaGetSymbolAddress((void**)&p_ccnt, g_ccnt);
    cudaGetSymbolAddress((void**)&p_lab,  g_lab);
    cudaGetSymbolAddress((void**)&p_cpro, g_cpro);
    cudaGetSymbolAddress((void**)&p_part, g_part);
    cudaGetSymbolAddress((void**)&p_pcnt, g_pcnt);

    cudaFuncSetAttribute(gemm_mma, cudaFuncAttributeMaxDynamicSharedMemorySize, GM_SMEM);

    // x -> residual stream
    copy_kernel<<<(NT * DD / 4 + 255) / 256, 256>>>((const float4*)x_in, (float4*)p_x, NT * DD / 4);

    // transpose + split all weights
    dim3 tb32(32, 8);
    for (int l = 0; l < LL; l++) {
        size_t base = (size_t)l * WT_LAYER;
        wsplit_kernel<<<dim3(256/32, 256/32), tb32>>>(Wq  + (size_t)l*DD*DD,   p_wth + base + WQ_OFF,  p_wtl + base + WQ_OFF,  256, 256);
        wsplit_kernel<<<dim3(512/32, 256/32), tb32>>>(Wkv + (size_t)l*DD*2*DD, p_wth + base + WKV_OFF, p_wtl + base + WKV_OFF, 256, 512);
        wsplit_kernel<<<dim3(256/32, 256/32), tb32>>>(Wo  + (size_t)l*DD*DD,   p_wth + base + WO_OFF,  p_wtl + base + WO_OFF,  256, 256);
        wsplit_kernel<<<dim3(1024/32, 256/32), tb32>>>(W1 + (size_t)l*DD*MFF,  p_wth + base + W1_OFF,  p_wtl + base + W1_OFF,  256, 1024);
        wsplit_kernel<<<dim3(256/32, 1024/32), tb32>>>(W2 + (size_t)l*MFF*DD,  p_wth + base + W2_OFF,  p_wtl + base + W2_OFF,  1024, 256);
    }

    for (int l = 0; l < LL; l++) {
        size_t wb = (size_t)l * WT_LAYER;
        const __nv_bfloat16* wqh  = p_wth + wb + WQ_OFF,  *wql  = p_wtl + wb + WQ_OFF;
        const __nv_bfloat16* wkvh = p_wth + wb + WKV_OFF, *wkvl = p_wtl + wb + WKV_OFF;
        const __nv_bfloat16* woh  = p_wth + wb + WO_OFF,  *wol  = p_wtl + wb + WO_OFF;
        const __nv_bfloat16* w1h  = p_wth + wb + W1_OFF,  *w1l  = p_wtl + wb + W1_OFF;
        const __nv_bfloat16* w2h  = p_wth + wb + W2_OFF,  *w2l  = p_wtl + wb + W2_OFF;

        // ln1 -> split xn
        ln_kernel<<<NT / 8, 256>>>(p_x, ln1g + l * DD, ln1b + l * DD, p_xnh, p_xnl);
        // q: [8192,256] -> split bf16
        gemm_mma<<<dim3(2, 64), 256, GM_SMEM>>>(p_xnh, p_xnl, wqh, wql,
            nullptr, nullptr, nullptr, p_qh, p_ql, NT, DD, DD, 0);
        // kv: [8192,512] -> split bf16
        gemm_mma<<<dim3(4, 64), 256, GM_SMEM>>>(p_xnh, p_xnl, wkvh, wkvl,
            nullptr, nullptr, nullptr, p_kvh, p_kvl, NT, 2 * DD, DD, 0);
        // attention (tensor-core) -> split ao
        attn_mma<<<dim3(NTOK / 128, HH, BB), 128>>>(p_qh, p_ql, p_kvh, p_kvl, p_aoh, p_aol);
        // out proj + bias + residual (into x)
        gemm_mma<<<dim3(2, 64), 256, GM_SMEM>>>(p_aoh, p_aol, woh, wol,
            bo + l * DD, p_x, p_x, nullptr, nullptr, NT, DD, DD, 0);
        // ln2 -> split xn
        ln_kernel<<<NT / 8, 256>>>(p_x, ln2g + l * DD, ln2b + l * DD, p_xnh, p_xnl);
        // ffn up + gelu -> split h
        gemm_mma<<<dim3(8, 64), 256, GM_SMEM>>>(p_xnh, p_xnl, w1h, w1l,
            b1 + l * MFF, nullptr, nullptr, p_hh, p_hl, NT, MFF, DD, 1);
        // ffn down + bias + residual (into x)
        gemm_mma<<<dim3(2, 64), 256, GM_SMEM>>>(p_hh, p_hl, w2h, w2l,
            b2 + l * DD, p_x, p_x, nullptr, nullptr, NT, DD, MFF, 0);
    }

    // ---- kmeans (fp32, deterministic) ----
    initcent_kernel<<<KC, 256>>>(p_x, p_cent);
    rowsumsq_kernel<<<NT / 8, 256>>>(p_x, p_xsq);

    for (int it = 0; it < KM_IT; it++) {
        rowsumsq_kernel<<<KC / 8, 256>>>(p_cent, p_csq);
        assign_kernel<<<NT / 128, 128>>>(p_x, p_cent, p_xsq, p_csq, p_lab);
        segsum1_kernel<<<dim3(SB, 2), 256>>>(p_x, p_lab, p_part, p_pcnt);
        segsum2_kernel<<<KC, 256>>>(p_part, p_pcnt, p_csum, p_ccnt);
        update_kernel<<<KC, 256>>>(p_cent, p_csum, p_ccnt);
    }
    rowsumsq_kernel<<<KC / 8, 256>>>(p_cent, p_csq);
    assign_kernel<<<NT / 128, 128>>>(p_x, p_cent, p_xsq, p_csq, p_lab);

    cproj_kernel<<<KC, 256>>>(p_cent, kW, kb, p_cpro);
    gather_kernel<<<NT, 256>>>(p_cpro, p_lab, out);
}

// round 7
// speedup vs baseline: 3.1500x; 1.0832x over previous
#include <cuda_runtime.h>
#include <cuda_bf16.h>
#include <math.h>
#include <stdint.h>

// ---------------- problem constants ----------------
#define BB     8
#define NTOK   1024
#define DD     256
#define LL     4
#define MFF    1024
#define HH     8
#define DHEAD  32
#define NT     (BB*NTOK)      // 8192 tokens
#define KC     64             // clusters
#define KM_IT  10
#define SB     64             // segsum point-blocks (128 points each)
#define QKVS   768            // combined qkv row stride

// weight-transpose scratch offsets (elements, per layer base = l*786432)
#define WT_LAYER 786432
#define WQKV_OFF 0
#define WO_OFF   196608
#define W1_OFF   262144
#define W2_OFF   524288

// ---------------- scratch (static device globals; no allocation allowed) ----
__device__ float g_x   [NT*DD];          // running residual stream (fp32)
__device__ __nv_bfloat16 g_qkvh[NT*QKVS];// q|k|v hi
__device__ __nv_bfloat16 g_qkvl[NT*QKVS];// q|k|v lo
__device__ __nv_bfloat16 g_xnh[NT*DD];   // layernorm out hi
__device__ __nv_bfloat16 g_xnl[NT*DD];   // layernorm out lo
__device__ __nv_bfloat16 g_aoh[NT*DD];   // attention out hi
__device__ __nv_bfloat16 g_aol[NT*DD];   // attention out lo
__device__ __nv_bfloat16 g_hh [NT*MFF];  // ffn hidden hi
__device__ __nv_bfloat16 g_hl [NT*MFF];  // ffn hidden lo
__device__ __nv_bfloat16 g_wth[LL*WT_LAYER]; // transposed weights hi
__device__ __nv_bfloat16 g_wtl[LL*WT_LAYER]; // transposed weights lo
__device__ float g_xsq [NT];
__device__ float g_cent[KC*DD];
__device__ float g_csq [KC];
__device__ float g_ccnt[KC];
__device__ int   g_lab [NT];
__device__ float g_cpro[KC*DD];
__device__ float g_part[SB*KC*DD];
__device__ float g_pcnt[SB*KC];

// ---------------- small helpers ----------------
__device__ __forceinline__ float gelu_f(float x) {
    return 0.5f * x * (1.0f + erff(x * 0.7071067811865476f));
}
__device__ __forceinline__ float warpSum(float v) {
    #pragma unroll
    for (int o = 16; o > 0; o >>= 1) v += __shfl_xor_sync(0xffffffffu, v, o);
    return v;
}
__device__ __forceinline__ float blockSum256(float v) {
    __shared__ float red[8];
    int t = threadIdx.x;
    v = warpSum(v);
    if ((t & 31) == 0) red[t >> 5] = v;
    __syncthreads();
    float s = 0.f;
    if (t == 0) {
        #pragma unroll
        for (int i = 0; i < 8; i++) s += red[i];
        red[0] = s;
    }
    __syncthreads();
    s = red[0];
    __syncthreads();
    return s;
}
__device__ __forceinline__ void splitf(float v, __nv_bfloat16& h, __nv_bfloat16& l) {
    h = __float2bfloat16(v);
    l = __float2bfloat16(v - __bfloat162float(h));
}
__device__ __forceinline__ void pack_split(float a, float b, uint32_t& hi, uint32_t& lo) {
    __nv_bfloat16 ah, al, bh, bl;
    splitf(a, ah, al); splitf(b, bh, bl);
    __nv_bfloat162 h2 = __halves2bfloat162(ah, bh);
    __nv_bfloat162 l2 = __halves2bfloat162(al, bl);
    hi = *(uint32_t*)&h2; lo = *(uint32_t*)&l2;
}
__device__ __forceinline__ uint32_t smem_u32(const void* p) {
    uint32_t a;
    asm("{ .reg .u64 t; cvta.to.shared.u64 t, %1; cvt.u32.u64 %0, t; }" : "=r"(a) : "l"(p));
    return a;
}

// ---------------- mma.sync helpers ----------------
__device__ __forceinline__ void ldm_x4(uint32_t* r, uint32_t addr) {
    asm volatile("ldmatrix.sync.aligned.m8n8.x4.shared.b16 {%0,%1,%2,%3}, [%4];"
                 : "=r"(r[0]), "=r"(r[1]), "=r"(r[2]), "=r"(r[3]) : "r"(addr));
}
__device__ __forceinline__ void mma_bf16(float* c, const uint32_t* a, const uint32_t* b) {
    asm volatile(
        "mma.sync.aligned.m16n8k16.row.col.f32.bf16.bf16.f32 "
        "{%0,%1,%2,%3}, {%4,%5,%6,%7}, {%8,%9}, {%0,%1,%2,%3};"
        : "+f"(c[0]), "+f"(c[1]), "+f"(c[2]), "+f"(c[3])
        : "r"(a[0]), "r"(a[1]), "r"(a[2]), "r"(a[3]), "r"(b[0]), "r"(b[1]));
}
__device__ __forceinline__ void cp16(uint32_t dst, const void* src) {
    asm volatile("cp.async.cg.shared.global [%0], [%1], 16;"
                 :: "r"(dst), "l"(src) : "memory");
}

// ---------------- layernorm: one WARP per row; emits split-bf16 --------------
__global__ void ln_kernel(const float* __restrict__ x, const float* __restrict__ g,
                          const float* __restrict__ b,
                          __nv_bfloat16* __restrict__ oh, __nv_bfloat16* __restrict__ ol) {
    int row  = (blockIdx.x * blockDim.x + threadIdx.x) >> 5;
    int lane = threadIdx.x & 31;
    const float* xp = x + (size_t)row * DD;
    float4 a = *(const float4*)&xp[lane * 4];
    float4 c = *(const float4*)&xp[128 + lane * 4];
    float s = a.x + a.y + a.z + a.w + c.x + c.y + c.z + c.w;
    float mean = warpSum(s) * (1.0f / DD);
    float4 da = make_float4(a.x - mean, a.y - mean, a.z - mean, a.w - mean);
    float4 dc = make_float4(c.x - mean, c.y - mean, c.z - mean, c.w - mean);
    float v = da.x*da.x + da.y*da.y + da.z*da.z + da.w*da.w
            + dc.x*dc.x + dc.y*dc.y + dc.z*dc.z + dc.w*dc.w;
    float rs = rsqrtf(warpSum(v) * (1.0f / DD) + 1e-5f);
    float4 g0 = *(const float4*)&g[lane * 4];
    float4 g1 = *(const float4*)&g[128 + lane * 4];
    float4 b0 = *(const float4*)&b[lane * 4];
    float4 b1 = *(const float4*)&b[128 + lane * 4];
    float o0[4] = { da.x*rs*g0.x + b0.x, da.y*rs*g0.y + b0.y,
                    da.z*rs*g0.z + b0.z, da.w*rs*g0.w + b0.w };
    float o1[4] = { dc.x*rs*g1.x + b1.x, dc.y*rs*g1.y + b1.y,
                    dc.z*rs*g1.z + b1.z, dc.w*rs*g1.w + b1.w };
    size_t base = (size_t)row * DD;
    #pragma unroll
    for (int j = 0; j < 2; j++) {
        uint32_t uh, ul;
        pack_split(o0[j*2+0], o0[j*2+1], uh, ul);
        *(uint32_t*)&oh[base + lane*4 + j*2] = uh;
        *(uint32_t*)&ol[base + lane*4 + j*2] = ul;
        pack_split(o1[j*2+0], o1[j*2+1], uh, ul);
        *(uint32_t*)&oh[base + 128 + lane*4 + j*2] = uh;
        *(uint32_t*)&ol[base + 128 + lane*4 + j*2] = ul;
    }
}

// ---------------- row sum-of-squares: one WARP per row of 256 ----------------
__global__ void rowsumsq_kernel(const float* __restrict__ x, float* __restrict__ out) {
    int row  = (blockIdx.x * blockDim.x + threadIdx.x) >> 5;
    int lane = threadIdx.x & 31;
    const float* xp = x + (size_t)row * DD;
    float4 a = *(const float4*)&xp[lane * 4];
    float4 c = *(const float4*)&xp[128 + lane * 4];
    float s = a.x*a.x + a.y*a.y + a.z*a.z + a.w*a.w
            + c.x*c.x + c.y*c.y + c.z*c.z + c.w*c.w;
    s = warpSum(s);
    if (lane == 0) out[row] = s;
}

// -------- weight transpose + bf16 split (batched over layers via blockIdx.z) -
__global__ void wsplit_kernel(const float* __restrict__ W,
                              __nv_bfloat16* __restrict__ oh, __nv_bfloat16* __restrict__ ol,
                              int K, int N, int strideW, int strideO) {
    __shared__ float tile[32][33];
    const int l = blockIdx.z;
    const float* Wl = W + (size_t)l * strideW;
    __nv_bfloat16* ohl = oh + (size_t)l * strideO;
    __nv_bfloat16* oll = ol + (size_t)l * strideO;
    int k0 = blockIdx.y * 32, n0 = blockIdx.x * 32;
    int tx = threadIdx.x, ty = threadIdx.y;   // 32 x 8
    #pragma unroll
    for (int j = 0; j < 4; j++)
        tile[ty + j*8][tx] = Wl[(size_t)(k0 + ty + j*8) * N + n0 + tx];
    __syncthreads();
    #pragma unroll
    for (int j = 0; j < 4; j++) {
        int n = ty + j*8;
        float v = tile[tx][n];
        size_t idx = (size_t)(n0 + n) * K + k0 + tx;
        __nv_bfloat16 h, l2; splitf(v, h, l2);
        ohl[idx] = h; oll[idx] = l2;
    }
}

// ---------------- split-bf16 GEMM on HMMA (mma.sync) -------------------------
#define PADK   40                       // smem row stride (bf16)
#define ARR_B  (128*PADK*2)
#define OFF_AH 0
#define OFF_AL (1*ARR_B)
#define OFF_BH (2*ARR_B)
#define OFF_BL (3*ARR_B)
#define BUF_B  (4*ARR_B)
#define GM_SMEM (2*BUF_B)               // 81920

__global__ __launch_bounds__(256)
void gemm_mma(const __nv_bfloat16* __restrict__ Ahi, const __nv_bfloat16* __restrict__ Alo,
              const __nv_bfloat16* __restrict__ Bhi, const __nv_bfloat16* __restrict__ Blo,
              const float* __restrict__ bias, const float* __restrict__ res,
              float* __restrict__ C,
              __nv_bfloat16* __restrict__ Chi, __nv_bfloat16* __restrict__ Clo,
              int M, int N, int K, int act) {
    extern __shared__ char smem[];
    const uint32_t sm = smem_u32(smem);
    const int m0 = blockIdx.y * 128;
    const int n0 = blockIdx.x * 128;
    const int t = threadIdx.x;
    const int wid = t >> 5, lid = t & 31;
    const int wm = wid & 3;
    const int wn = wid >> 2;
    const int NC = K >> 5;

    float acc[2][8][4];
    #pragma unroll
    for (int i = 0; i < 2; i++)
        #pragma unroll
        for (int j = 0; j < 8; j++)
            #pragma unroll
            for (int q = 0; q < 4; q++) acc[i][j][q] = 0.f;

    auto issueChunk = [&](int c, int buf) {
        const int kb = c * 32;
        const uint32_t base = sm + buf * BUF_B;
        #pragma unroll
        for (int i = 0; i < 2; i++) {
            int idx = i * 256 + t;
            int r = idx >> 2, seg = idx & 3;
            uint32_t so = (uint32_t)(r * PADK + seg * 8) * 2;
            size_t ga = (size_t)(m0 + r) * K + kb + seg * 8;
            size_t gb = (size_t)(n0 + r) * K + kb + seg * 8;
            cp16(base + OFF_AH + so, &Ahi[ga]);
            cp16(base + OFF_AL + so, &Alo[ga]);
            cp16(base + OFF_BH + so, &Bhi[gb]);
            cp16(base + OFF_BL + so, &Blo[gb]);
        }
        asm volatile("cp.async.commit_group;" ::: "memory");
    };

    issueChunk(0, 0);

    for (int c = 0; c < NC; c++) {
        const int buf = c & 1;
        if (c + 1 < NC) {
            issueChunk(c + 1, buf ^ 1);
            asm volatile("cp.async.wait_group 1;" ::: "memory");
        } else {
            asm volatile("cp.async.wait_group 0;" ::: "memory");
        }
        __syncthreads();

        const uint32_t base = sm + buf * BUF_B;
        #pragma unroll
        for (int kk = 0; kk < 32; kk += 16) {
            uint32_t a_h[2][4], a_l[2][4];
            #pragma unroll
            for (int at = 0; at < 2; at++) {
                int row = wm * 32 + at * 16 + (lid & 15);
                int col = kk + (lid >> 4) * 8;
                uint32_t ro = (uint32_t)(row * PADK + col) * 2;
                ldm_x4(a_h[at], base + OFF_AH + ro);
                ldm_x4(a_l[at], base + OFF_AL + ro);
            }
            uint32_t b_h[8][2], b_l[8][2];
            #pragma unroll
            for (int np = 0; np < 4; np++) {
                int quad = lid >> 3, qr = lid & 7;
                int nrow = wn * 64 + np * 16 + (quad >> 1) * 8 + qr;
                int col  = kk + (quad & 1) * 8;
                uint32_t ro = (uint32_t)(nrow * PADK + col) * 2;
                uint32_t r4[4];
                ldm_x4(r4, base + OFF_BH + ro);
                b_h[np*2][0] = r4[0]; b_h[np*2][1] = r4[1];
                b_h[np*2+1][0] = r4[2]; b_h[np*2+1][1] = r4[3];
                ldm_x4(r4, base + OFF_BL + ro);
                b_l[np*2][0] = r4[0]; b_l[np*2][1] = r4[1];
                b_l[np*2+1][0] = r4[2]; b_l[np*2+1][1] = r4[3];
            }
            #pragma unroll
            for (int at = 0; at < 2; at++)
                #pragma unroll
                for (int nt = 0; nt < 8; nt++) {
                    mma_bf16(acc[at][nt], a_h[at], b_h[nt]);
                    mma_bf16(acc[at][nt], a_h[at], b_l[nt]);
                    mma_bf16(acc[at][nt], a_l[at], b_h[nt]);
                }
        }
        __syncthreads();
    }

    // ---- epilogue ----
    #pragma unroll
    for (int at = 0; at < 2; at++) {
        #pragma unroll
        for (int nt = 0; nt < 8; nt++) {
            int col = n0 + wn * 64 + nt * 8 + (lid & 3) * 2;
            #pragma unroll
            for (int half = 0; half < 2; half++) {
                int row = m0 + wm * 32 + at * 16 + (lid >> 2) + half * 8;
                float v0 = acc[at][nt][half * 2 + 0];
                float v1 = acc[at][nt][half * 2 + 1];
                size_t gi = (size_t)row * N + col;
                if (bias) { v0 += bias[col]; v1 += bias[col + 1]; }
                if (act)  { v0 = gelu_f(v0); v1 = gelu_f(v1); }
                if (res)  { float2 r2 = *(const float2*)&res[gi]; v0 += r2.x; v1 += r2.y; }
                if (C) {
                    *(float2*)&C[gi] = make_float2(v0, v1);
                } else {
                    uint32_t uh, ul;
                    pack_split(v0, v1, uh, ul);
                    *(uint32_t*)&Chi[gi] = uh;
                    *(uint32_t*)&Clo[gi] = ul;
                }
            }
        }
    }
}

// ---------------- tensor-core flash attention (split-bf16, combined qkv) -----
#define AQS 40     // Q/K smem row stride (bf16)
#define AVS 72     // V^T smem row stride (bf16)

__global__ __launch_bounds__(128)
void attn_mma(const __nv_bfloat16* __restrict__ qkvh, const __nv_bfloat16* __restrict__ qkvl,
              __nv_bfloat16* __restrict__ aoh, __nv_bfloat16* __restrict__ aol) {
    __shared__ __nv_bfloat16 Qh[128*AQS], Ql[128*AQS];
    __shared__ __nv_bfloat16 Kh[64*AQS],  Kl[64*AQS];
    __shared__ __nv_bfloat16 Vh[32*AVS],  Vl[32*AVS];
    const int h = blockIdx.y, b = blockIdx.z;
    const int t = threadIdx.x, w = t >> 5, lid = t & 31;
    const int q0 = blockIdx.x * 128;
    const int quad = lid >> 3, qr = lid & 7;
    const uint32_t sQh = smem_u32(Qh), sQl = smem_u32(Ql);
    const uint32_t sKh = smem_u32(Kh), sKl = smem_u32(Kl);
    const uint32_t sVh = smem_u32(Vh), sVl = smem_u32(Vl);
    const float scale = 0.17677669529663687f;   // 1/sqrt(32)

    // ---- stage Q tile (128 x 32) ----
    #pragma unroll
    for (int i = 0; i < 4; i++) {
        int idx = i * 128 + t; int r = idx >> 2, seg = idx & 3;
        size_t g = ((size_t)(b * NTOK) + q0 + r) * QKVS + h * DHEAD + seg * 8;
        *(uint4*)(Qh + r * AQS + seg * 8) = *(const uint4*)&qkvh[g];
        *(uint4*)(Ql + r * AQS + seg * 8) = *(const uint4*)&qkvl[g];
    }

    float O[2][4][4];
    #pragma unroll
    for (int a1 = 0; a1 < 2; a1++)
        #pragma unroll
        for (int a2 = 0; a2 < 4; a2++)
            #pragma unroll
            for (int a3 = 0; a3 < 4; a3++) O[a1][a2][a3] = 0.f;
    float mrow[2][2] = {{-1e30f,-1e30f},{-1e30f,-1e30f}};
    float lrow[2][2] = {{0.f,0.f},{0.f,0.f}};

    for (int kt = 0; kt < NTOK; kt += 64) {
        // K tile via cp.async (64 x 32 hi/lo)
        #pragma unroll
        for (int i = 0; i < 2; i++) {
            int idx = i * 128 + t; int r = idx >> 2, seg = idx & 3;
            size_t g = ((size_t)(b * NTOK) + kt + r) * QKVS + 256 + h * DHEAD + seg * 8;
            cp16(sKh + (uint32_t)(r * AQS + seg * 8) * 2, &qkvh[g]);
            cp16(sKl + (uint32_t)(r * AQS + seg * 8) * 2, &qkvl[g]);
        }
        asm volatile("cp.async.commit_group;" ::: "memory");
        // V tile transposed
        {
            int r2 = lid, seg = w;
            size_t g0 = ((size_t)(b * NTOK) + kt + 2 * r2) * QKVS + 512 + h * DHEAD + seg * 8;
            uint4 vh0 = *(const uint4*)&qkvh[g0];
            uint4 vh1 = *(const uint4*)&qkvh[g0 + QKVS];
            uint4 vl0 = *(const uint4*)&qkvl[g0];
            uint4 vl1 = *(const uint4*)&qkvl[g0 + QKVS];
            const __nv_bfloat16* h0 = (const __nv_bfloat16*)&vh0;
            const __nv_bfloat16* h1 = (const __nv_bfloat16*)&vh1;
            const __nv_bfloat16* l0 = (const __nv_bfloat16*)&vl0;
            const __nv_bfloat16* l1 = (const __nv_bfloat16*)&vl1;
            #pragma unroll
            for (int j = 0; j < 8; j++) {
                __nv_bfloat162 ph = __halves2bfloat162(h0[j], h1[j]);
                __nv_bfloat162 pl = __halves2bfloat162(l0[j], l1[j]);
                int off = (seg * 8 + j) * AVS + 2 * r2;
                *(uint32_t*)(Vh + off) = *(uint32_t*)&ph;
                *(uint32_t*)(Vl + off) = *(uint32_t*)&pl;
            }
        }
        asm volatile("cp.async.wait_group 0;" ::: "memory");
        __syncthreads();

        // ---- S = Q K^T ----
        float S[2][8][4];
        #pragma unroll
        for (int a1 = 0; a1 < 2; a1++)
            #pragma unroll
            for (int a2 = 0; a2 < 8; a2++)
                #pragma unroll
                for (int a3 = 0; a3 < 4; a3++) S[a1][a2][a3] = 0.f;

        #pragma unroll
        for (int kk = 0; kk < 2; kk++) {
            uint32_t qa_h[2][4], qa_l[2][4];
            #pragma unroll
            for (int at = 0; at < 2; at++) {
                uint32_t ro = (uint32_t)((w * 32 + at * 16 + (lid & 15)) * AQS
                                         + kk * 16 + (lid >> 4) * 8) * 2;
                ldm_x4(qa_h[at], sQh + ro);
                ldm_x4(qa_l[at], sQl + ro);
            }
            uint32_t kb_h[8][2], kb_l[8][2];
            #pragma unroll
            for (int np = 0; np < 4; np++) {
                uint32_t ro = (uint32_t)((np * 16 + (quad >> 1) * 8 + qr) * AQS
                                         + kk * 16 + (quad & 1) * 8) * 2;
                uint32_t r4[4];
                ldm_x4(r4, sKh + ro);
                kb_h[np*2][0] = r4[0]; kb_h[np*2][1] = r4[1];
                kb_h[np*2+1][0] = r4[2]; kb_h[np*2+1][1] = r4[3];
                ldm_x4(r4, sKl + ro);
                kb_l[np*2][0] = r4[0]; kb_l[np*2][1] = r4[1];
                kb_l[np*2+1][0] = r4[2]; kb_l[np*2+1][1] = r4[3];
            }
            #pragma unroll
            for (int at = 0; at < 2; at++)
                #pragma unroll
                for (int nt = 0; nt < 8; nt++) {
                    mma_bf16(S[at][nt], qa_h[at], kb_h[nt]);
                    mma_bf16(S[at][nt], qa_h[at], kb_l[nt]);
                    mma_bf16(S[at][nt], qa_l[at], kb_h[nt]);
                }
        }

        // ---- online softmax + P*V ----
        #pragma unroll
        for (int at = 0; at < 2; at++) {
            float tm0 = -1e30f, tm1 = -1e30f;
            #pragma unroll
            for (int nt = 0; nt < 8; nt++) {
                S[at][nt][0] *= scale; S[at][nt][1] *= scale;
                S[at][nt][2] *= scale; S[at][nt][3] *= scale;
                tm0 = fmaxf(tm0, fmaxf(S[at][nt][0], S[at][nt][1]));
                tm1 = fmaxf(tm1, fmaxf(S[at][nt][2], S[at][nt][3]));
            }
            tm0 = fmaxf(tm0, __shfl_xor_sync(0xffffffffu, tm0, 1));
            tm0 = fmaxf(tm0, __shfl_xor_sync(0xffffffffu, tm0, 2));
            tm1 = fmaxf(tm1, __shfl_xor_sync(0xffffffffu, tm1, 1));
            tm1 = fmaxf(tm1, __shfl_xor_sync(0xffffffffu, tm1, 2));
            float m0n = fmaxf(mrow[at][0], tm0);
            float m1n = fmaxf(mrow[at][1], tm1);
            float c0 = __expf(mrow[at][0] - m0n);
            float c1 = __expf(mrow[at][1] - m1n);
            mrow[at][0] = m0n; mrow[at][1] = m1n;

            float ls0 = 0.f, ls1 = 0.f;
            uint32_t pah[4][4], pal[4][4];
            #pragma unroll
            for (int g = 0; g < 4; g++) {
                float p00 = __expf(S[at][2*g  ][0] - m0n);
                float p01 = __expf(S[at][2*g  ][1] - m0n);
                float p02 = __expf(S[at][2*g  ][2] - m1n);
                float p03 = __expf(S[at][2*g  ][3] - m1n);
                float p10 = __expf(S[at][2*g+1][0] - m0n);
                float p11 = __expf(S[at][2*g+1][1] - m0n);
                float p12 = __expf(S[at][2*g+1][2] - m1n);
                float p13 = __expf(S[at][2*g+1][3] - m1n);
                ls0 += p00 + p01 + p10 + p11;
                ls1 += p02 + p03 + p12 + p13;
                pack_split(p00, p01, pah[g][0], pal[g][0]);
                pack_split(p02, p03, pah[g][1], pal[g][1]);
                pack_split(p10, p11, pah[g][2], pal[g][2]);
                pack_split(p12, p13, pah[g][3], pal[g][3]);
            }
            ls0 += __shfl_xor_sync(0xffffffffu, ls0, 1);
            ls0 += __shfl_xor_sync(0xffffffffu, ls0, 2);
            ls1 += __shfl_xor_sync(0xffffffffu, ls1, 1);
            ls1 += __shfl_xor_sync(0xffffffffu, ls1, 2);
            lrow[at][0] = lrow[at][0] * c0 + ls0;
            lrow[at][1] = lrow[at][1] * c1 + ls1;
            #pragma unroll
            for (int vn = 0; vn < 4; vn++) {
                O[at][vn][0] *= c0; O[at][vn][1] *= c0;
                O[at][vn][2] *= c1; O[at][vn][3] *= c1;
            }
            #pragma unroll
            for (int g = 0; g < 4; g++) {
                uint32_t vb_h[4][2], vb_l[4][2];
                #pragma unroll
                for (int np = 0; np < 2; np++) {
                    uint32_t ro = (uint32_t)((np * 16 + (quad >> 1) * 8 + qr) * AVS
                                             + g * 16 + (quad & 1) * 8) * 2;
                    uint32_t r4[4];
                    ldm_x4(r4, sVh + ro);
                    vb_h[np*2][0] = r4[0]; vb_h[np*2][1] = r4[1];
                    vb_h[np*2+1][0] = r4[2]; vb_h[np*2+1][1] = r4[3];
                    ldm_x4(r4, sVl + ro);
                    vb_l[np*2][0] = r4[0]; vb_l[np*2][1] = r4[1];
                    vb_l[np*2+1][0] = r4[2]; vb_l[np*2+1][1] = r4[3];
                }
                #pragma unroll
                for (int vn = 0; vn < 4; vn++) {
                    mma_bf16(O[at][vn], pah[g], vb_h[vn]);
                    mma_bf16(O[at][vn], pah[g], vb_l[vn]);
                    mma_bf16(O[at][vn], pal[g], vb_h[vn]);
                }
            }
        }
        __syncthreads();
    }

    // ---- normalize + write ----
    #pragma unroll
    for (int at = 0; at < 2; at++) {
        float i0 = 1.f / lrow[at][0];
        float i1 = 1.f / lrow[at][1];
        int r0 = q0 + w * 32 + at * 16 + (lid >> 2);
        #pragma unroll
        for (int vn = 0; vn < 4; vn++) {
            int col = h * DHEAD + vn * 8 + (lid & 3) * 2;
            size_t g0 = ((size_t)(b * NTOK) + r0) * DD + col;
            size_t g1 = g0 + (size_t)8 * DD;
            uint32_t uh, ul;
            pack_split(O[at][vn][0] * i0, O[at][vn][1] * i0, uh, ul);
            *(uint32_t*)&aoh[g0] = uh; *(uint32_t*)&aol[g0] = ul;
            pack_split(O[at][vn][2] * i1, O[at][vn][3] * i1, uh, ul);
            *(uint32_t*)&aoh[g1] = uh; *(uint32_t*)&aol[g1] = ul;
        }
    }
}

// ---------------- kmeans ----------------
__global__ void initcent_kernel(const float* __restrict__ x, float* __restrict__ cent) {
    cent[(size_t)blockIdx.x * DD + threadIdx.x] = x[(size_t)blockIdx.x * DD + threadIdx.x];
}

// assign: 32 points/block, 128 threads, thread = (point, 16-center group)
__global__ __launch_bounds__(128)
void assign_kernel(const float* __restrict__ x, const float* __restrict__ cent,
                   const float* __restrict__ xsq, const float* __restrict__ csq,
                   int* __restrict__ lab) {
    __shared__ float Xs[32][33];
    __shared__ float Cs[64][32];
    __shared__ float bd[32][4];
    __shared__ int   bc[32][4];
    const int t = threadIdx.x;
    const int p = t & 31, cg = t >> 5;
    const int p0 = blockIdx.x * 32;

    float dot[16];
    #pragma unroll
    for (int c = 0; c < 16; c++) dot[c] = 0.f;

    for (int dc = 0; dc < DD; dc += 32) {
        #pragma unroll
        for (int i = 0; i < 2; i++) {               // 256 float4 / 128 thr
            int idx = i * 128 + t;
            int r = idx >> 3, c4 = (idx & 7) * 4;
            float4 v = *(const float4*)&x[(size_t)(p0 + r) * DD + dc + c4];
            Xs[r][c4 + 0] = v.x; Xs[r][c4 + 1] = v.y;
            Xs[r][c4 + 2] = v.z; Xs[r][c4 + 3] = v.w;
        }
        #pragma unroll
        for (int i = 0; i < 4; i++) {               // 512 float4 / 128 thr
            int idx = i * 128 + t;
            int r = idx >> 3, c4 = (idx & 7) * 4;
            *(float4*)&Cs[r][c4] = *(const float4*)&cent[(size_t)r * DD + dc + c4];
        }
        __syncthreads();
        #pragma unroll 4
        for (int d = 0; d < 32; d++) {
            float xv = Xs[p][d];
            #pragma unroll
            for (int c = 0; c < 16; c++) dot[c] += xv * Cs[cg * 16 + c][d];
        }
        __syncthreads();
    }

    float xs = xsq[p0 + p];
    float best = 3.4e38f;
    int bl = 0;
    #pragma unroll
    for (int c = 0; c < 16; c++) {
        float dd = xs - 2.f * dot[c] + csq[cg * 16 + c];
        if (dd < best) { best = dd; bl = cg * 16 + c; }   // strict < = first index
    }
    bd[p][cg] = best; bc[p][cg] = bl;
    __syncthreads();
    if (t < 32) {
        float b2 = bd[t][0]; int l2 = bc[t][0];
        #pragma unroll
        for (int g = 1; g < 4; g++)
            if (bd[t][g] < b2) { b2 = bd[t][g]; l2 = bc[t][g]; }
        lab[p0 + t] = l2;
    }
}

__global__ __launch_bounds__(256)
void segsum1_kernel(const float* __restrict__ x, const int* __restrict__ lab,
                    float* __restrict__ part, float* __restrict__ pcnt) {
    const int blk = blockIdx.x;
    const int c0  = blockIdx.y * 32;
    const int t = threadIdx.x;
    __shared__ float ps[32][DD];
    __shared__ int labs[128];
    #pragma unroll
    for (int i = 0; i < 32; i++) ps[i][t] = 0.f;
    if (t < 128) labs[t] = lab[blk * 128 + t];
    __syncthreads();
    const int p0 = blk * 128;
    for (int i = 0; i < 128; i++) {
        int l = labs[i] - c0;
        if ((unsigned)l < 32u)
            ps[l][t] += x[(size_t)(p0 + i) * DD + t];
    }
    for (int c = 0; c < 32; c++)
        part[((size_t)blk * KC + c0 + c) * DD + t] = ps[c][t];
    if (t < 32) {
        int cnt = 0;
        for (int i = 0; i < 128; i++) cnt += (labs[i] == c0 + t);
        pcnt[blk * KC + c0 + t] = (float)cnt;
    }
}

// reduce partials + update center + csq for next iteration (fused)
__global__ __launch_bounds__(256)
void update_csq_kernel(const float* __restrict__ part, const float* __restrict__ pcnt,
                       float* __restrict__ cent, float* __restrict__ csq) {
    const int c = blockIdx.x, t = threadIdx.x;
    __shared__ float scnt;
    float acc = 0.f;
    for (int b2 = 0; b2 < SB; b2++) acc += part[((size_t)b2 * KC + c) * DD + t];
    if (t == 0) {
        float cc = 0.f;
        for (int b2 = 0; b2 < SB; b2++) cc += pcnt[b2 * KC + c];
        scnt = cc;
    }
    __syncthreads();
    float cv = cent[(size_t)c * DD + t];
    float nv = (scnt > 0.f) ? acc / fmaxf(scnt, 1.f) : cv;
    cent[(size_t)c * DD + t] = nv;
    float s = blockSum256(nv * nv);
    if (t == 0) csq[c] = s;
}

__global__ void cproj_kernel(const float* __restrict__ cent, const float* __restrict__ kW,
                             const float* __restrict__ kb, float* __restrict__ cpro) {
    __shared__ float cr[DD];
    int c = blockIdx.x, t = threadIdx.x;
    cr[t] = cent[(size_t)c * DD + t];
    __syncthreads();
    float acc = kb[t];
    for (int d = 0; d < DD; d++) acc += cr[d] * kW[(size_t)d * DD + t];
    cpro[(size_t)c * DD + t] = acc;
}

__global__ void gather_kernel(const float* __restrict__ cproj, const int* __restrict__ lab,
                              float* __restrict__ out) {
    int p = blockIdx.x, t = threadIdx.x;
    out[(size_t)p * DD + t] = cproj[(size_t)lab[p] * DD + t];
}

// ---------------- host orchestration ----------------
extern "C" void kernel_launch(void* const* d_in, const int* in_sizes, int n_in,
                              void* d_out, int out_size) {
    const float* x_in = (const float*)d_in[0];
    const float* ln1g = (const float*)d_in[1];
    const float* ln1b = (const float*)d_in[2];
    const float* Wq   = (const float*)d_in[3];
    const float* Wkv  = (const float*)d_in[4];
    const float* Wo   = (const float*)d_in[5];
    const float* bo   = (const float*)d_in[6];
    const float* ln2g = (const float*)d_in[7];
    const float* ln2b = (const float*)d_in[8];
    const float* W1   = (const float*)d_in[9];
    const float* b1   = (const float*)d_in[10];
    const float* W2   = (const float*)d_in[11];
    const float* b2   = (const float*)d_in[12];
    const float* kW   = (const float*)d_in[13];
    const float* kb   = (const float*)d_in[14];
    float* out = (float*)d_out;

    float *p_x, *p_xsq, *p_cent, *p_csq, *p_cpro, *p_part, *p_pcnt;
    __nv_bfloat16 *p_qkvh, *p_qkvl;
    __nv_bfloat16 *p_xnh, *p_xnl, *p_aoh, *p_aol, *p_hh, *p_hl, *p_wth, *p_wtl;
    int *p_lab;
    cudaGetSymbolAddress((void**)&p_x,    g_x);
    cudaGetSymbolAddress((void**)&p_qkvh, g_qkvh);
    cudaGetSymbolAddress((void**)&p_qkvl, g_qkvl);
    cudaGetSymbolAddress((void**)&p_xnh,  g_xnh);
    cudaGetSymbolAddress((void**)&p_xnl,  g_xnl);
    cudaGetSymbolAddress((void**)&p_aoh,  g_aoh);
    cudaGetSymbolAddress((void**)&p_aol,  g_aol);
    cudaGetSymbolAddress((void**)&p_hh,   g_hh);
    cudaGetSymbolAddress((void**)&p_hl,   g_hl);
    cudaGetSymbolAddress((void**)&p_wth,  g_wth);
    cudaGetSymbolAddress((void**)&p_wtl,  g_wtl);
    cudaGetSymbolAddress((void**)&p_xsq,  g_xsq);
    cudaGetSymbolAddress((void**)&p_cent, g_cent);
    cudaGetSymbolAddress((void**)&p_csq,  g_csq);
    cudaGetSymbolAddress((void**)&p_lab,  g_lab);
    cudaGetSymbolAddress((void**)&p_cpro, g_cpro);
    cudaGetSymbolAddress((void**)&p_part, g_part);
    cudaGetSymbolAddress((void**)&p_pcnt, g_pcnt);

    cudaFuncSetAttribute(gemm_mma, cudaFuncAttributeMaxDynamicSharedMemorySize, GM_SMEM);

    // transpose + split all weights (batched over layers: 5 launches)
    dim3 tb32(32, 8);
    wsplit_kernel<<<dim3(8,  8, LL), tb32>>>(Wq,  p_wth + WQKV_OFF,         p_wtl + WQKV_OFF,         256, 256,  DD*DD,     WT_LAYER);
    wsplit_kernel<<<dim3(16, 8, LL), tb32>>>(Wkv, p_wth + WQKV_OFF + 65536, p_wtl + WQKV_OFF + 65536, 256, 512,  DD*2*DD,   WT_LAYER);
    wsplit_kernel<<<dim3(8,  8, LL), tb32>>>(Wo,  p_wth + WO_OFF,           p_wtl + WO_OFF,           256, 256,  DD*DD,     WT_LAYER);
    wsplit_kernel<<<dim3(32, 8, LL), tb32>>>(W1,  p_wth + W1_OFF,           p_wtl + W1_OFF,           256, 1024, DD*MFF,    WT_LAYER);
    wsplit_kernel<<<dim3(8, 32, LL), tb32>>>(W2,  p_wth + W2_OFF,           p_wtl + W2_OFF,           1024, 256, MFF*DD,    WT_LAYER);

    for (int l = 0; l < LL; l++) {
        size_t wb = (size_t)l * WT_LAYER;
        const __nv_bfloat16* wqkvh = p_wth + wb + WQKV_OFF, *wqkvl = p_wtl + wb + WQKV_OFF;
        const __nv_bfloat16* woh   = p_wth + wb + WO_OFF,   *wol   = p_wtl + wb + WO_OFF;
        const __nv_bfloat16* w1h   = p_wth + wb + W1_OFF,   *w1l   = p_wtl + wb + W1_OFF;
        const __nv_bfloat16* w2h   = p_wth + wb + W2_OFF,   *w2l   = p_wtl + wb + W2_OFF;
        const float* xsrc = (l == 0) ? x_in : p_x;

        // ln1 -> split xn
        ln_kernel<<<NT / 8, 256>>>(xsrc, ln1g + l * DD, ln1b + l * DD, p_xnh, p_xnl);
        // fused qkv: [8192,768] -> split bf16
        gemm_mma<<<dim3(6, 64), 256, GM_SMEM>>>(p_xnh, p_xnl, wqkvh, wqkvl,
            nullptr, nullptr, nullptr, p_qkvh, p_qkvl, NT, QKVS, DD, 0);
        // attention (tensor-core) -> split ao
        attn_mma<<<dim3(NTOK / 128, HH, BB), 128>>>(p_qkvh, p_qkvl, p_aoh, p_aol);
        // out proj + bias + residual (into x)
        gemm_mma<<<dim3(2, 64), 256, GM_SMEM>>>(p_aoh, p_aol, woh, wol,
            bo + l * DD, xsrc, p_x, nullptr, nullptr, NT, DD, DD, 0);
        // ln2 -> split xn
        ln_kernel<<<NT / 8, 256>>>(p_x, ln2g + l * DD, ln2b + l * DD, p_xnh, p_xnl);
        // ffn up + gelu -> split h
        gemm_mma<<<dim3(8, 64), 256, GM_SMEM>>>(p_xnh, p_xnl, w1h, w1l,
            b1 + l * MFF, nullptr, nullptr, p_hh, p_hl, NT, MFF, DD, 1);
        // ffn down + bias + residual (into x)
        gemm_mma<<<dim3(2, 64), 256, GM_SMEM>>>(p_hh, p_hl, w2h, w2l,
            b2 + l * DD, p_x, p_x, nullptr, nullptr, NT, DD, MFF, 0);
    }

    // ---- kmeans (fp32, deterministic) ----
    initcent_kernel<<<KC, 256>>>(p_x, p_cent);
    rowsumsq_kernel<<<NT / 8, 256>>>(p_x, p_xsq);
    rowsumsq_kernel<<<KC / 8, 256>>>(p_cent, p_csq);

    for (int it = 0; it < KM_IT; it++) {
        assign_kernel<<<NT / 32, 128>>>(p_x, p_cent, p_xsq, p_csq, p_lab);
        segsum1_kernel<<<dim3(SB, 2), 256>>>(p_x, p_lab, p_part, p_pcnt);
        update_csq_kernel<<<KC, 256>>>(p_part, p_pcnt, p_cent, p_csq);
    }
    assign_kernel<<<NT / 32, 128>>>(p_x, p_cent, p_xsq, p_csq, p_lab);

    cproj_kernel<<<KC, 256>>>(p_cent, kW, kb, p_cpro);
    gather_kernel<<<NT, 256>>>(p_cpro, p_lab, out);
}